// round 2
// baseline (speedup 1.0000x reference)
#include <cuda_runtime.h>
#include <math.h>

// Problem constants
#define DFEAT 1024
#define MROWS 3072                 // B * 3 channels
#define PLANE (MROWS * DFEAT)      // 3,145,728 floats per layer plane
#define NLAYERS 17

// ---------------- device scratch (no runtime allocation) ---------------------
__device__ float g_X0[PLANE];                        // prepped input
__device__ float g_Y[PLANE];                         // pre-projection Y of current layer
__device__ float g_xt[53477376];                     // 17 * PLANE : xs[l] planes

// ---------------- f32x2 helpers ----------------------------------------------
static __device__ __forceinline__ unsigned long long pk2(float x, float y) {
    unsigned long long r;
    asm("mov.b64 %0, {%1,%2};" : "=l"(r) : "f"(x), "f"(y));
    return r;
}
static __device__ __forceinline__ void upk2(unsigned long long v, float& x, float& y) {
    asm("mov.b64 {%0,%1}, %2;" : "=f"(x), "=f"(y) : "l"(v));
}
static __device__ __forceinline__ unsigned long long ffma2(unsigned long long a,
                                                           unsigned long long b,
                                                           unsigned long long c) {
    unsigned long long d;
    asm("fma.rn.f32x2 %0, %1, %2, %3;" : "=l"(d) : "l"(a), "l"(b), "l"(c));
    return d;
}

// ---------------- prep: channel-2 vh (16,64) -> v (64,16) --------------------
__global__ void prep_kernel(const float* __restrict__ Xin) {
    int idx = blockIdx.x * 256 + threadIdx.x;
    if (idx >= PLANE) return;
    int d  = idx & 1023;
    int bc = idx >> 10;
    int c  = bc % 3;
    float v;
    if (c == 2) {
        int b = bc / 3;
        int dim = d >> 4, k = d & 15;
        v = Xin[((size_t)(b * 3 + 2)) * 1024 + k * 64 + dim];
    } else {
        v = Xin[idx];
    }
    g_X0[idx] = v;
}

// ---------------- GEMM: C[m,e] = sum_d A[m,d]*W[e,d]; residual epilogue ------
// 128(M) x 64(N) tile, 256 threads, thread tile 8x4, f32x2-packed accumulators.
// layer==0: Y = C. layer>0: Y = A + h*relu(C + bias).
// Y -> g_Y always; channel-1 rows (m%3==1) also -> output plane (no projection).
__global__ __launch_bounds__(256, 2) void gemm_kernel(
    int inPlane, const float* __restrict__ W, const float* __restrict__ bias,
    const float* __restrict__ hp, int outPlane, int layer)
{
    __shared__ float As[16][132];
    __shared__ float Bs[16][68];

    const float* A = (inPlane < 0) ? g_X0 : (g_xt + (size_t)inPlane * PLANE);
    float* PL = g_xt + (size_t)outPlane * PLANE;

    int tid = threadIdx.x;
    int m0 = blockIdx.y * 128;
    int n0 = blockIdx.x * 64;
    int tx = tid & 15, ty = tid >> 4;
    int i0 = ty * 8, j0 = tx * 4;

    int rA0 = tid >> 2;              // 0..63
    int rA1 = rA0 + 64;              // 64..127
    int kA  = (tid & 3) * 4;         // 0,4,8,12
    int rB  = tid >> 2;              // 0..63
    int kB  = (tid & 3) * 4;

    const float* Ag = A + (size_t)m0 * 1024;
    const float* Wg = W + (size_t)n0 * 1024;

    unsigned long long acc[4][4];
#pragma unroll
    for (int i = 0; i < 4; i++)
#pragma unroll
        for (int j = 0; j < 4; j++) acc[i][j] = 0ull;

    float4 na0 = *(const float4*)(Ag + (size_t)rA0 * 1024 + kA);
    float4 na1 = *(const float4*)(Ag + (size_t)rA1 * 1024 + kA);
    float4 nb  = *(const float4*)(Wg + (size_t)rB  * 1024 + kB);

    for (int k0 = 0; k0 < 1024; k0 += 16) {
        As[kA + 0][rA0] = na0.x; As[kA + 1][rA0] = na0.y;
        As[kA + 2][rA0] = na0.z; As[kA + 3][rA0] = na0.w;
        As[kA + 0][rA1] = na1.x; As[kA + 1][rA1] = na1.y;
        As[kA + 2][rA1] = na1.z; As[kA + 3][rA1] = na1.w;
        Bs[kB + 0][rB]  = nb.x;  Bs[kB + 1][rB]  = nb.y;
        Bs[kB + 2][rB]  = nb.z;  Bs[kB + 3][rB]  = nb.w;
        __syncthreads();

        if (k0 + 16 < 1024) {
            na0 = *(const float4*)(Ag + (size_t)rA0 * 1024 + k0 + 16 + kA);
            na1 = *(const float4*)(Ag + (size_t)rA1 * 1024 + k0 + 16 + kA);
            nb  = *(const float4*)(Wg + (size_t)rB  * 1024 + k0 + 16 + kB);
        }

#pragma unroll
        for (int kk = 0; kk < 16; kk++) {
            float4 av0 = *(const float4*)&As[kk][i0];
            float4 av1 = *(const float4*)&As[kk][i0 + 4];
            float4 bv  = *(const float4*)&Bs[kk][j0];
            unsigned long long a2[4] = { pk2(av0.x, av0.y), pk2(av0.z, av0.w),
                                         pk2(av1.x, av1.y), pk2(av1.z, av1.w) };
            unsigned long long b2[4] = { pk2(bv.x, bv.x), pk2(bv.y, bv.y),
                                         pk2(bv.z, bv.z), pk2(bv.w, bv.w) };
#pragma unroll
            for (int i2 = 0; i2 < 4; i2++)
#pragma unroll
                for (int j = 0; j < 4; j++)
                    acc[i2][j] = ffma2(a2[i2], b2[j], acc[i2][j]);
        }
        __syncthreads();
    }

    // epilogue
    float hv = 0.f;
    float4 b4 = make_float4(0.f, 0.f, 0.f, 0.f);
    if (layer > 0) {
        hv = *hp;
        b4 = *(const float4*)(bias + n0 + j0);
    }

#pragma unroll
    for (int i2 = 0; i2 < 4; i2++) {
        float lo[4], hi[4];
#pragma unroll
        for (int j = 0; j < 4; j++) upk2(acc[i2][j], lo[j], hi[j]);
        int m_lo = m0 + i0 + i2 * 2;

#pragma unroll
        for (int p = 0; p < 2; p++) {
            int m = m_lo + p;
            float c0 = p ? hi[0] : lo[0];
            float c1 = p ? hi[1] : lo[1];
            float c2 = p ? hi[2] : lo[2];
            float c3 = p ? hi[3] : lo[3];
            float4 y;
            if (layer > 0) {
                float4 ao = *(const float4*)(A + (size_t)m * 1024 + n0 + j0);
                y.x = ao.x + hv * fmaxf(c0 + b4.x, 0.f);
                y.y = ao.y + hv * fmaxf(c1 + b4.y, 0.f);
                y.z = ao.z + hv * fmaxf(c2 + b4.z, 0.f);
                y.w = ao.w + hv * fmaxf(c3 + b4.w, 0.f);
            } else {
                y = make_float4(c0, c1, c2, c3);
            }
            *(float4*)(g_Y + (size_t)m * 1024 + n0 + j0) = y;
            if (m % 3 == 1)
                *(float4*)(PL + (size_t)m * 1024 + n0 + j0) = y;
        }
    }
}

// ---------------- polar projection: one warp per 64x16 matrix ----------------
// U = A * (A^T A)^(-1/2) via coupled Newton-Schulz on the 16x16 Gram.
#define PNW 4
__global__ __launch_bounds__(128) void polar_kernel(int plane, int niter) {
    __shared__ float AsP[PNW][16][68];     // A col-major: [col][row], padded
    __shared__ float MsP[PNW][3][16][20];  // Y, Z, T 16x16, rows padded to 20

    int w = threadIdx.x >> 5, lane = threadIdx.x & 31;
    int idx = blockIdx.x * PNW + w;        // 0..2047
    int b = idx >> 1, ch = (idx & 1) * 2;

    const float* src = g_Y + (size_t)(b * 3 + ch) * 1024;
    float* dst = g_xt + (size_t)plane * PLANE + (size_t)(b * 3 + ch) * 1024;

    float (*A)[68]  = AsP[w];
    float (*Ym)[20] = MsP[w][0];
    float (*Zm)[20] = MsP[w][1];
    float (*Tm)[20] = MsP[w][2];

    // load A (64x16 row-major in gmem) into smem col-major
    int r0 = lane * 2;
#pragma unroll
    for (int q = 0; q < 4; q++) {
        float4 v0 = *(const float4*)(src + r0 * 16 + q * 4);
        float4 v1 = *(const float4*)(src + (r0 + 1) * 16 + q * 4);
        A[q * 4 + 0][r0] = v0.x; A[q * 4 + 1][r0] = v0.y;
        A[q * 4 + 2][r0] = v0.z; A[q * 4 + 3][r0] = v0.w;
        A[q * 4 + 0][r0 + 1] = v1.x; A[q * 4 + 1][r0 + 1] = v1.y;
        A[q * 4 + 2][r0 + 1] = v1.z; A[q * 4 + 3][r0 + 1] = v1.w;
    }
    __syncwarp();

    // G = A^T A : lane owns 2x4 tile (rows i0,i0+1; cols j0..j0+3)
    int i0 = (lane >> 2) * 2, j0 = (lane & 3) * 4;
    float g0[4] = {0, 0, 0, 0}, g1[4] = {0, 0, 0, 0};
#pragma unroll
    for (int r = 0; r < 64; r += 4) {
        float4 a0 = *(const float4*)&A[i0][r];
        float4 a1 = *(const float4*)&A[i0 + 1][r];
#pragma unroll
        for (int t = 0; t < 4; t++) {
            float4 aj = *(const float4*)&A[j0 + t][r];
            g0[t] += a0.x * aj.x + a0.y * aj.y + a0.z * aj.z + a0.w * aj.w;
            g1[t] += a1.x * aj.x + a1.y * aj.y + a1.z * aj.z + a1.w * aj.w;
        }
    }
    *(float4*)&Ym[i0][j0]     = make_float4(g0[0], g0[1], g0[2], g0[3]);
    *(float4*)&Ym[i0 + 1][j0] = make_float4(g1[0], g1[1], g1[2], g1[3]);
    __syncwarp();

    // s = ||G||_inf  (>= lambda_max)
    float rs = 0.f;
    if (lane < 16) {
#pragma unroll
        for (int j = 0; j < 16; j++) rs += fabsf(Ym[lane][j]);
    }
#pragma unroll
    for (int off = 16; off; off >>= 1)
        rs = fmaxf(rs, __shfl_xor_sync(0xffffffffu, rs, off));
    float invs = 1.0f / rs;

    // Y0 = G/s ; Z0 = I
#pragma unroll
    for (int t = 0; t < 4; t++) { g0[t] *= invs; g1[t] *= invs; }
    *(float4*)&Ym[i0][j0]     = make_float4(g0[0], g0[1], g0[2], g0[3]);
    *(float4*)&Ym[i0 + 1][j0] = make_float4(g1[0], g1[1], g1[2], g1[3]);
    *(float4*)&Zm[i0][j0] = make_float4(i0 == j0 ? 1.f : 0.f, i0 == j0 + 1 ? 1.f : 0.f,
                                        i0 == j0 + 2 ? 1.f : 0.f, i0 == j0 + 3 ? 1.f : 0.f);
    *(float4*)&Zm[i0 + 1][j0] = make_float4(i0 + 1 == j0 ? 1.f : 0.f, i0 + 1 == j0 + 1 ? 1.f : 0.f,
                                            i0 + 1 == j0 + 2 ? 1.f : 0.f, i0 + 1 == j0 + 3 ? 1.f : 0.f);
    __syncwarp();

    for (int it = 0; it < niter; it++) {
        // T = (3I - Z*Y)/2
        float t0[4] = {0, 0, 0, 0}, t1[4] = {0, 0, 0, 0};
#pragma unroll
        for (int k = 0; k < 16; k++) {
            float z0 = Zm[i0][k], z1 = Zm[i0 + 1][k];
            float4 y4 = *(const float4*)&Ym[k][j0];
            t0[0] += z0 * y4.x; t0[1] += z0 * y4.y; t0[2] += z0 * y4.z; t0[3] += z0 * y4.w;
            t1[0] += z1 * y4.x; t1[1] += z1 * y4.y; t1[2] += z1 * y4.z; t1[3] += z1 * y4.w;
        }
#pragma unroll
        for (int t = 0; t < 4; t++) {
            t0[t] = ((i0     == j0 + t) ? (3.0f - t0[t]) : -t0[t]) * 0.5f;
            t1[t] = ((i0 + 1 == j0 + t) ? (3.0f - t1[t]) : -t1[t]) * 0.5f;
        }
        *(float4*)&Tm[i0][j0]     = make_float4(t0[0], t0[1], t0[2], t0[3]);
        *(float4*)&Tm[i0 + 1][j0] = make_float4(t1[0], t1[1], t1[2], t1[3]);
        __syncwarp();

        // Ynew = Y*T ; Znew = T*Z
        float yn0[4] = {0, 0, 0, 0}, yn1[4] = {0, 0, 0, 0};
        float zn0[4] = {0, 0, 0, 0}, zn1[4] = {0, 0, 0, 0};
#pragma unroll
        for (int k = 0; k < 16; k++) {
            float4 t4 = *(const float4*)&Tm[k][j0];
            float ya = Ym[i0][k], yb = Ym[i0 + 1][k];
            yn0[0] += ya * t4.x; yn0[1] += ya * t4.y; yn0[2] += ya * t4.z; yn0[3] += ya * t4.w;
            yn1[0] += yb * t4.x; yn1[1] += yb * t4.y; yn1[2] += yb * t4.z; yn1[3] += yb * t4.w;
            float4 z4 = *(const float4*)&Zm[k][j0];
            float ta = Tm[i0][k], tb = Tm[i0 + 1][k];
            zn0[0] += ta * z4.x; zn0[1] += ta * z4.y; zn0[2] += ta * z4.z; zn0[3] += ta * z4.w;
            zn1[0] += tb * z4.x; zn1[1] += tb * z4.y; zn1[2] += tb * z4.z; zn1[3] += tb * z4.w;
        }
        __syncwarp();
        *(float4*)&Ym[i0][j0]     = make_float4(yn0[0], yn0[1], yn0[2], yn0[3]);
        *(float4*)&Ym[i0 + 1][j0] = make_float4(yn1[0], yn1[1], yn1[2], yn1[3]);
        *(float4*)&Zm[i0][j0]     = make_float4(zn0[0], zn0[1], zn0[2], zn0[3]);
        *(float4*)&Zm[i0 + 1][j0] = make_float4(zn1[0], zn1[1], zn1[2], zn1[3]);
        __syncwarp();
    }

    // U = A * Z * s^(-1/2)   (Z -> (G/s)^(-1/2) = sqrt(s) G^(-1/2))
    float isq = rsqrtf(rs);
    float u0[16], u1[16];
#pragma unroll
    for (int c = 0; c < 16; c++) { u0[c] = 0.f; u1[c] = 0.f; }
#pragma unroll
    for (int k = 0; k < 16; k++) {
        float a0 = A[k][r0], a1 = A[k][r0 + 1];
#pragma unroll
        for (int cq = 0; cq < 4; cq++) {
            float4 z4 = *(const float4*)&Zm[k][cq * 4];
            u0[cq * 4 + 0] += a0 * z4.x; u0[cq * 4 + 1] += a0 * z4.y;
            u0[cq * 4 + 2] += a0 * z4.z; u0[cq * 4 + 3] += a0 * z4.w;
            u1[cq * 4 + 0] += a1 * z4.x; u1[cq * 4 + 1] += a1 * z4.y;
            u1[cq * 4 + 2] += a1 * z4.z; u1[cq * 4 + 3] += a1 * z4.w;
        }
    }
#pragma unroll
    for (int cq = 0; cq < 4; cq++) {
        *(float4*)(dst + r0 * 16 + cq * 4) =
            make_float4(u0[cq * 4] * isq, u0[cq * 4 + 1] * isq,
                        u0[cq * 4 + 2] * isq, u0[cq * 4 + 3] * isq);
        *(float4*)(dst + (r0 + 1) * 16 + cq * 4) =
            make_float4(u1[cq * 4] * isq, u1[cq * 4 + 1] * isq,
                        u1[cq * 4 + 2] * isq, u1[cq * 4 + 3] * isq);
    }
}

// ---------------- X_transformed: [l][bcd] -> [bcd][l] coalesced --------------
__global__ void xt_kernel(float* __restrict__ out) {
    __shared__ float tile[256][18];
    int base = blockIdx.x * 256;
    int tid = threadIdx.x;
#pragma unroll
    for (int l = 0; l < 17; l++)
        tile[tid][l] = g_xt[(size_t)l * PLANE + base + tid];
    __syncthreads();
    float* o = out + (size_t)base * 17;
    for (int i = tid; i < 256 * 17; i += 256)
        o[i] = tile[i / 17][i % 17];
}

// ---------------- reconstruct + classify + softmax ----------------------------
__global__ __launch_bounds__(128) void classify_kernel(
    const float* __restrict__ Wc, const float* __restrict__ bc,
    float* __restrict__ out, int off_log)
{
    __shared__ float sU[1024], sS[256], sV[1024], sT[1024];
    __shared__ float sZ[4096];
    __shared__ float red[10 * 136];
    __shared__ float slog[10];

    int b = blockIdx.x, tid = threadIdx.x;
    const float* base = g_xt + (size_t)16 * PLANE + (size_t)b * 3 * 1024;

    for (int i = tid; i < 1024; i += 128) { sU[i] = base[i]; sV[i] = base[2048 + i]; }
    for (int i = tid; i < 256; i += 128) sS[i] = base[1024 + i];
    __syncthreads();

    // T = U * S  (64x16)
    for (int e = tid; e < 1024; e += 128) {
        int r = e >> 4, c = e & 15;
        float sum = 0.f;
#pragma unroll
        for (int k = 0; k < 16; k++) sum += sU[r * 16 + k] * sS[k * 16 + c];
        sT[e] = sum;
    }
    __syncthreads();

    // Z = T * V^T  (64x64)
    for (int e = tid; e < 4096; e += 128) {
        int r = e >> 6, q = e & 63;
        float sum = 0.f;
#pragma unroll
        for (int c = 0; c < 16; c++) sum += sT[r * 16 + c] * sV[q * 16 + c];
        sZ[e] = sum;
    }
    __syncthreads();

    float acc[10];
#pragma unroll
    for (int n = 0; n < 10; n++) acc[n] = 0.f;
    for (int e = tid; e < 4096; e += 128) {
        float z = sZ[e];
#pragma unroll
        for (int n = 0; n < 10; n++) acc[n] += z * Wc[n * 4096 + e];
    }
#pragma unroll
    for (int n = 0; n < 10; n++) red[n * 136 + tid] = acc[n];
    __syncthreads();
    if (tid < 10) {
        float s = bc[tid];
        for (int j = 0; j < 128; j++) s += red[tid * 136 + j];
        slog[tid] = s;
    }
    __syncthreads();
    if (tid == 0) {
        float mx = slog[0];
        for (int n = 1; n < 10; n++) mx = fmaxf(mx, slog[n]);
        float ex[10]; float se = 0.f;
        for (int n = 0; n < 10; n++) { ex[n] = expf(slog[n] - mx); se += ex[n]; }
        float inv = 1.f / se;
        for (int n = 0; n < 10; n++) {
            out[b * 10 + n] = ex[n] * inv;                       // X_predicted
            if (off_log >= 0) out[off_log + b * 10 + n] = slog[n]; // X_classified
        }
    }
}

// ---------------- launch ------------------------------------------------------
extern "C" void kernel_launch(void* const* d_in, const int* in_sizes, int n_in,
                              void* d_out, int out_size) {
    const float* X  = (const float*)d_in[0];
    const float* h  = (const float*)d_in[1];
    const float* W0 = (const float*)d_in[2];
    const float* Ws = (const float*)d_in[3];
    const float* bs = (const float*)d_in[4];
    const float* Wc = (const float*)d_in[5];
    const float* bc = (const float*)d_in[6];
    float* out = (float*)d_out;

    // output layout: [pred(10240) | logits(10240) | transformed(53477376)]
    int off_log = -1, off_xt = -1;
    if (out_size >= 10240 + 10240 + 53477376) { off_log = 10240; off_xt = 20480; }
    else if (out_size == 10240 + 53477376)    { off_xt = 10240; }
    else if (out_size >= 20480)               { off_log = 10240; }

    prep_kernel<<<PLANE / 256, 256>>>(X);

    dim3 ggrid(16, 24);
    gemm_kernel<<<ggrid, 256>>>(-1, W0, nullptr, h, 0, 0);
    polar_kernel<<<512, 128>>>(0, 22);
    for (int l = 1; l <= 16; l++) {
        gemm_kernel<<<ggrid, 256>>>(l - 1, Ws + (size_t)(l - 1) * 1048576,
                                    bs + (size_t)(l - 1) * 1024, h, l, l);
        polar_kernel<<<512, 128>>>(l, 13);
    }

    if (off_xt >= 0)
        xt_kernel<<<PLANE / 256, 256>>>(out + off_xt);
    classify_kernel<<<1024, 128>>>(Wc, bc, out, off_log);
}

// round 4
// speedup vs baseline: 1.2575x; 1.2575x over previous
#include <cuda_runtime.h>
#include <cuda_bf16.h>
#include <math.h>
#include <stdint.h>

#define PLANE 3145728            // 3072 * 1024
#define WELEMS 17825792          // 17 * 1024 * 1024

// ---------------- device scratch --------------------------------------------
__device__ float g_Y[PLANE];                 // pre-projection Y of current layer
__device__ float g_xt[17 * PLANE];           // xs[l] planes (fp32)
__device__ __nv_bfloat16 g_bXhi[2][PLANE];   // ping-pong split-bf16 X
__device__ __nv_bfloat16 g_bXlo[2][PLANE];
__device__ __nv_bfloat16 g_bWhi[WELEMS];     // split-bf16 weights (W0 at 0, Ws at 1..16)
__device__ __nv_bfloat16 g_bWlo[WELEMS];

// ---------------- helpers -----------------------------------------------------
static __device__ __forceinline__ uint32_t smem_u32(const void* p) {
    return (uint32_t)__cvta_generic_to_shared(p);
}
static __device__ __forceinline__ void ldsm4(uint32_t* r, uint32_t addr) {
    asm volatile("ldmatrix.sync.aligned.m8n8.x4.shared.b16 {%0,%1,%2,%3}, [%4];"
        : "=r"(r[0]), "=r"(r[1]), "=r"(r[2]), "=r"(r[3]) : "r"(addr));
}
static __device__ __forceinline__ void mma16816(float* c, const uint32_t* a,
                                                uint32_t b0, uint32_t b1) {
    asm volatile("mma.sync.aligned.m16n8k16.row.col.f32.bf16.bf16.f32 "
        "{%0,%1,%2,%3}, {%4,%5,%6,%7}, {%8,%9}, {%0,%1,%2,%3};"
        : "+f"(c[0]), "+f"(c[1]), "+f"(c[2]), "+f"(c[3])
        : "r"(a[0]), "r"(a[1]), "r"(a[2]), "r"(a[3]), "r"(b0), "r"(b1));
}

// ---------------- weight split conversion ------------------------------------
__global__ void wconv_kernel(const float* __restrict__ W0, const float* __restrict__ Ws) {
    size_t i = (size_t)blockIdx.x * 256 + threadIdx.x;
    if (i >= (size_t)WELEMS) return;
    float v = (i < 1048576) ? W0[i] : Ws[i - 1048576];
    __nv_bfloat16 h = __float2bfloat16_rn(v);
    g_bWhi[i] = h;
    g_bWlo[i] = __float2bfloat16_rn(v - __bfloat162float(h));
}

// ---------------- prep: split-bf16 of input (ch2 transposed) -----------------
__global__ void prep_kernel(const float* __restrict__ Xin) {
    int idx = blockIdx.x * 256 + threadIdx.x;
    if (idx >= PLANE) return;
    int d  = idx & 1023;
    int bc = idx >> 10;
    int c  = bc % 3;
    float v;
    if (c == 2) {
        int b = bc / 3;
        int dim = d >> 4, k = d & 15;
        v = Xin[((size_t)(b * 3 + 2)) * 1024 + k * 64 + dim];
    } else {
        v = Xin[idx];
    }
    __nv_bfloat16 h = __float2bfloat16_rn(v);
    g_bXhi[0][idx] = h;
    g_bXlo[0][idx] = __float2bfloat16_rn(v - __bfloat162float(h));
}

// ---------------- split-bf16 mma.sync GEMM + fused epilogue ------------------
// D[m,n] = sum_d A[m,d]*W[n,d] via 3 bf16 products (AhBh + AhBl + AlBh).
// Tile 128x128, K-chunk 32, 2-stage cp.async pipeline, 8 warps (2M x 4N).
#define MAT_STRIDE_B 80          // bytes per smem row (40 bf16, pad for ldmatrix)
#define MAT_BYTES (128 * MAT_STRIDE_B)   // 10240
#define STAGE_BYTES (4 * MAT_BYTES)      // 40960
#define SMEM_TOTAL_G (2 * STAGE_BYTES)   // 81920

__global__ __launch_bounds__(256, 2) void tgemm_kernel(
    const float* __restrict__ bias, const float* __restrict__ hp, int layer)
{
    extern __shared__ __align__(16) char smem[];
    uint32_t sb = smem_u32(smem);

    int tid = threadIdx.x;
    int wid = tid >> 5, lane = tid & 31;
    int bx = blockIdx.x;
    int m0 = (bx >> 3) * 128;
    int n0 = (bx & 7) * 128;

    int par = layer & 1;
    const __nv_bfloat16* mats0 = g_bXhi[par];
    const __nv_bfloat16* mats1 = g_bXlo[par];
    const __nv_bfloat16* mats2 = g_bWhi + (size_t)layer * 1048576;
    const __nv_bfloat16* mats3 = g_bWlo + (size_t)layer * 1048576;

    int q = tid >> 6;                  // 0:Ahi 1:Alo 2:Bhi 3:Blo
    int t64 = tid & 63;
    const __nv_bfloat16* gsrc =
        ((q == 0) ? mats0 : (q == 1) ? mats1 : (q == 2) ? mats2 : mats3)
        + (size_t)((q < 2) ? m0 : n0) * 1024;

    float acc[4][4][4];
#pragma unroll
    for (int i = 0; i < 4; i++)
#pragma unroll
        for (int j = 0; j < 4; j++)
#pragma unroll
            for (int k = 0; k < 4; k++) acc[i][j][k] = 0.f;

    auto issue = [&](int c, int st) {
        const __nv_bfloat16* src = gsrc + c * 32;
        uint32_t dstb = sb + st * STAGE_BYTES + q * MAT_BYTES;
#pragma unroll
        for (int u = 0; u < 8; u++) {
            int s = t64 + u * 64;           // 0..511
            int row = s >> 2, seg = s & 3;
            uint32_t dst = dstb + row * MAT_STRIDE_B + seg * 16;
            const __nv_bfloat16* gp = src + (size_t)row * 1024 + seg * 8;
            asm volatile("cp.async.cg.shared.global [%0], [%1], 16;"
                :: "r"(dst), "l"(gp));
        }
        asm volatile("cp.async.commit_group;" ::: "memory");
    };

    issue(0, 0);

    int mw = (wid >> 2) * 64, nw = (wid & 3) * 32;
    int lrow = (lane & 7) + ((lane >> 3) & 1) * 8;
    int lcolB = ((lane >> 4) * 8) * 2;   // byte offset of ldmatrix col

    for (int c = 0; c < 32; c++) {
        int st = c & 1;
        if (c + 1 < 32) {
            issue(c + 1, st ^ 1);
            asm volatile("cp.async.wait_group 1;" ::: "memory");
        } else {
            asm volatile("cp.async.wait_group 0;" ::: "memory");
        }
        __syncthreads();

        uint32_t base = sb + st * STAGE_BYTES;
#pragma unroll
        for (int ks = 0; ks < 2; ks++) {
            int colb = ks * 32 + lcolB;
            uint32_t bh[2][4], bl[2][4];
#pragma unroll
            for (int nb = 0; nb < 2; nb++) {
                uint32_t addr = base + 2 * MAT_BYTES +
                                (nw + nb * 16 + lrow) * MAT_STRIDE_B + colb;
                ldsm4(bh[nb], addr);
                ldsm4(bl[nb], addr + MAT_BYTES);
            }
#pragma unroll
            for (int ma = 0; ma < 4; ma++) {
                uint32_t ah[4], al[4];
                uint32_t aaddr = base + (mw + ma * 16 + lrow) * MAT_STRIDE_B + colb;
                ldsm4(ah, aaddr);
                ldsm4(al, aaddr + MAT_BYTES);
#pragma unroll
                for (int na = 0; na < 4; na++) {
                    int nb = na >> 1, hi = na & 1;
                    uint32_t b0h = bh[nb][hi], b1h = bh[nb][2 + hi];
                    uint32_t b0l = bl[nb][hi], b1l = bl[nb][2 + hi];
                    mma16816(acc[ma][na], ah, b0h, b1h);
                    mma16816(acc[ma][na], ah, b0l, b1l);
                    mma16816(acc[ma][na], al, b0h, b1h);
                }
            }
        }
        __syncthreads();
    }

    // ---- fused epilogue from register fragments
    float hv = 0.f;
    const float* Xprev = nullptr;
    if (layer > 0) { hv = *hp; Xprev = g_xt + (size_t)(layer - 1) * PLANE; }
    float* PL = g_xt + (size_t)layer * PLANE;
    int opar = (layer + 1) & 1;
    int g = lane >> 2, t2 = (lane & 3) * 2;

#pragma unroll
    for (int ma = 0; ma < 4; ma++) {
#pragma unroll
        for (int na = 0; na < 4; na++) {
            int n = n0 + nw + na * 8 + t2;
            float2 b2 = make_float2(0.f, 0.f);
            if (layer > 0) b2 = *(const float2*)(bias + n);
#pragma unroll
            for (int hh = 0; hh < 2; hh++) {
                int m = m0 + mw + ma * 16 + g + hh * 8;
                float cx = acc[ma][na][hh * 2], cy = acc[ma][na][hh * 2 + 1];
                float2 y;
                if (layer > 0) {
                    float2 xo = *(const float2*)(Xprev + (size_t)m * 1024 + n);
                    y.x = xo.x + hv * fmaxf(cx + b2.x, 0.f);
                    y.y = xo.y + hv * fmaxf(cy + b2.y, 0.f);
                } else {
                    y.x = cx; y.y = cy;
                }
                *(float2*)(g_Y + (size_t)m * 1024 + n) = y;
                if (m % 3 == 1) {
                    *(float2*)(PL + (size_t)m * 1024 + n) = y;
                    __nv_bfloat16 hx = __float2bfloat16_rn(y.x);
                    __nv_bfloat16 hy = __float2bfloat16_rn(y.y);
                    __nv_bfloat162 h2; h2.x = hx; h2.y = hy;
                    *(__nv_bfloat162*)(&g_bXhi[opar][(size_t)m * 1024 + n]) = h2;
                    __nv_bfloat162 l2;
                    l2.x = __float2bfloat16_rn(y.x - __bfloat162float(hx));
                    l2.y = __float2bfloat16_rn(y.y - __bfloat162float(hy));
                    *(__nv_bfloat162*)(&g_bXlo[opar][(size_t)m * 1024 + n]) = l2;
                }
            }
        }
    }
}

// ---------------- polar projection (Newton-Schulz on 16x16 Gram) -------------
#define PNW 4
__global__ __launch_bounds__(128) void polar_kernel(int plane, int niter, int opar) {
    __shared__ float AsP[PNW][16][68];
    __shared__ float MsP[PNW][3][16][20];

    int w = threadIdx.x >> 5, lane = threadIdx.x & 31;
    int idx = blockIdx.x * PNW + w;
    int b = idx >> 1, ch = (idx & 1) * 2;

    const float* src = g_Y + (size_t)(b * 3 + ch) * 1024;
    size_t doff = (size_t)(b * 3 + ch) * 1024;
    float* dst = g_xt + (size_t)plane * PLANE + doff;

    float (*A)[68]  = AsP[w];
    float (*Ym)[20] = MsP[w][0];
    float (*Zm)[20] = MsP[w][1];
    float (*Tm)[20] = MsP[w][2];

    int r0 = lane * 2;
#pragma unroll
    for (int qq = 0; qq < 4; qq++) {
        float4 v0 = *(const float4*)(src + r0 * 16 + qq * 4);
        float4 v1 = *(const float4*)(src + (r0 + 1) * 16 + qq * 4);
        A[qq * 4 + 0][r0] = v0.x; A[qq * 4 + 1][r0] = v0.y;
        A[qq * 4 + 2][r0] = v0.z; A[qq * 4 + 3][r0] = v0.w;
        A[qq * 4 + 0][r0 + 1] = v1.x; A[qq * 4 + 1][r0 + 1] = v1.y;
        A[qq * 4 + 2][r0 + 1] = v1.z; A[qq * 4 + 3][r0 + 1] = v1.w;
    }
    __syncwarp();

    int i0 = (lane >> 2) * 2, j0 = (lane & 3) * 4;
    float g0[4] = {0, 0, 0, 0}, g1[4] = {0, 0, 0, 0};
#pragma unroll
    for (int r = 0; r < 64; r += 4) {
        float4 a0 = *(const float4*)&A[i0][r];
        float4 a1 = *(const float4*)&A[i0 + 1][r];
#pragma unroll
        for (int t = 0; t < 4; t++) {
            float4 aj = *(const float4*)&A[j0 + t][r];
            g0[t] += a0.x * aj.x + a0.y * aj.y + a0.z * aj.z + a0.w * aj.w;
            g1[t] += a1.x * aj.x + a1.y * aj.y + a1.z * aj.z + a1.w * aj.w;
        }
    }
    *(float4*)&Ym[i0][j0]     = make_float4(g0[0], g0[1], g0[2], g0[3]);
    *(float4*)&Ym[i0 + 1][j0] = make_float4(g1[0], g1[1], g1[2], g1[3]);
    __syncwarp();

    float rs = 0.f;
    if (lane < 16) {
#pragma unroll
        for (int j = 0; j < 16; j++) rs += fabsf(Ym[lane][j]);
    }
#pragma unroll
    for (int off = 16; off; off >>= 1)
        rs = fmaxf(rs, __shfl_xor_sync(0xffffffffu, rs, off));
    float invs = 1.0f / rs;

#pragma unroll
    for (int t = 0; t < 4; t++) { g0[t] *= invs; g1[t] *= invs; }
    *(float4*)&Ym[i0][j0]     = make_float4(g0[0], g0[1], g0[2], g0[3]);
    *(float4*)&Ym[i0 + 1][j0] = make_float4(g1[0], g1[1], g1[2], g1[3]);
    *(float4*)&Zm[i0][j0] = make_float4(i0 == j0 ? 1.f : 0.f, i0 == j0 + 1 ? 1.f : 0.f,
                                        i0 == j0 + 2 ? 1.f : 0.f, i0 == j0 + 3 ? 1.f : 0.f);
    *(float4*)&Zm[i0 + 1][j0] = make_float4(i0 + 1 == j0 ? 1.f : 0.f, i0 + 1 == j0 + 1 ? 1.f : 0.f,
                                            i0 + 1 == j0 + 2 ? 1.f : 0.f, i0 + 1 == j0 + 3 ? 1.f : 0.f);
    __syncwarp();

    for (int it = 0; it < niter; it++) {
        float t0[4] = {0, 0, 0, 0}, t1[4] = {0, 0, 0, 0};
#pragma unroll
        for (int k = 0; k < 16; k++) {
            float z0 = Zm[i0][k], z1 = Zm[i0 + 1][k];
            float4 y4 = *(const float4*)&Ym[k][j0];
            t0[0] += z0 * y4.x; t0[1] += z0 * y4.y; t0[2] += z0 * y4.z; t0[3] += z0 * y4.w;
            t1[0] += z1 * y4.x; t1[1] += z1 * y4.y; t1[2] += z1 * y4.z; t1[3] += z1 * y4.w;
        }
#pragma unroll
        for (int t = 0; t < 4; t++) {
            t0[t] = ((i0     == j0 + t) ? (3.0f - t0[t]) : -t0[t]) * 0.5f;
            t1[t] = ((i0 + 1 == j0 + t) ? (3.0f - t1[t]) : -t1[t]) * 0.5f;
        }
        *(float4*)&Tm[i0][j0]     = make_float4(t0[0], t0[1], t0[2], t0[3]);
        *(float4*)&Tm[i0 + 1][j0] = make_float4(t1[0], t1[1], t1[2], t1[3]);
        __syncwarp();

        float yn0[4] = {0, 0, 0, 0}, yn1[4] = {0, 0, 0, 0};
        float zn0[4] = {0, 0, 0, 0}, zn1[4] = {0, 0, 0, 0};
#pragma unroll
        for (int k = 0; k < 16; k++) {
            float4 t4 = *(const float4*)&Tm[k][j0];
            float ya = Ym[i0][k], yb = Ym[i0 + 1][k];
            yn0[0] += ya * t4.x; yn0[1] += ya * t4.y; yn0[2] += ya * t4.z; yn0[3] += ya * t4.w;
            yn1[0] += yb * t4.x; yn1[1] += yb * t4.y; yn1[2] += yb * t4.z; yn1[3] += yb * t4.w;
            float4 z4 = *(const float4*)&Zm[k][j0];
            float ta = Tm[i0][k], tb = Tm[i0 + 1][k];
            zn0[0] += ta * z4.x; zn0[1] += ta * z4.y; zn0[2] += ta * z4.z; zn0[3] += ta * z4.w;
            zn1[0] += tb * z4.x; zn1[1] += tb * z4.y; zn1[2] += tb * z4.z; zn1[3] += tb * z4.w;
        }
        __syncwarp();
        *(float4*)&Ym[i0][j0]     = make_float4(yn0[0], yn0[1], yn0[2], yn0[3]);
        *(float4*)&Ym[i0 + 1][j0] = make_float4(yn1[0], yn1[1], yn1[2], yn1[3]);
        *(float4*)&Zm[i0][j0]     = make_float4(zn0[0], zn0[1], zn0[2], zn0[3]);
        *(float4*)&Zm[i0 + 1][j0] = make_float4(zn1[0], zn1[1], zn1[2], zn1[3]);
        __syncwarp();
    }

    float isq = rsqrtf(rs);
    float u0[16], u1[16];
#pragma unroll
    for (int c = 0; c < 16; c++) { u0[c] = 0.f; u1[c] = 0.f; }
#pragma unroll
    for (int k = 0; k < 16; k++) {
        float a0 = A[k][r0], a1 = A[k][r0 + 1];
#pragma unroll
        for (int cq = 0; cq < 4; cq++) {
            float4 z4 = *(const float4*)&Zm[k][cq * 4];
            u0[cq * 4 + 0] += a0 * z4.x; u0[cq * 4 + 1] += a0 * z4.y;
            u0[cq * 4 + 2] += a0 * z4.z; u0[cq * 4 + 3] += a0 * z4.w;
            u1[cq * 4 + 0] += a1 * z4.x; u1[cq * 4 + 1] += a1 * z4.y;
            u1[cq * 4 + 2] += a1 * z4.z; u1[cq * 4 + 3] += a1 * z4.w;
        }
    }
#pragma unroll
    for (int c = 0; c < 16; c++) { u0[c] *= isq; u1[c] *= isq; }

    // fp32 U out
#pragma unroll
    for (int cq = 0; cq < 4; cq++) {
        *(float4*)(dst + r0 * 16 + cq * 4) =
            make_float4(u0[cq * 4], u0[cq * 4 + 1], u0[cq * 4 + 2], u0[cq * 4 + 3]);
        *(float4*)(dst + (r0 + 1) * 16 + cq * 4) =
            make_float4(u1[cq * 4], u1[cq * 4 + 1], u1[cq * 4 + 2], u1[cq * 4 + 3]);
    }

    // split-bf16 out: pack via smem for coalesced writes
    uint32_t phi[16], plo[16];
#pragma unroll
    for (int row2 = 0; row2 < 2; row2++) {
        float* u = row2 ? u1 : u0;
#pragma unroll
        for (int cq = 0; cq < 8; cq++) {
            float a = u[2 * cq], bb = u[2 * cq + 1];
            __nv_bfloat16 ha = __float2bfloat16_rn(a);
            __nv_bfloat16 hb = __float2bfloat16_rn(bb);
            __nv_bfloat162 hp2; hp2.x = ha; hp2.y = hb;
            phi[row2 * 8 + cq] = *(uint32_t*)&hp2;
            __nv_bfloat162 lp2;
            lp2.x = __float2bfloat16_rn(a - __bfloat162float(ha));
            lp2.y = __float2bfloat16_rn(bb - __bfloat162float(hb));
            plo[row2 * 8 + cq] = *(uint32_t*)&lp2;
        }
    }
    __syncwarp();
    uint32_t* pk = (uint32_t*)&A[0][0];
#pragma unroll
    for (int row2 = 0; row2 < 2; row2++)
#pragma unroll
        for (int cq = 0; cq < 8; cq++) pk[(r0 + row2) * 8 + cq] = phi[row2 * 8 + cq];
    __syncwarp();
    {
        uint32_t* gd = (uint32_t*)(g_bXhi[opar] + doff);
#pragma unroll
        for (int i = 0; i < 16; i++) gd[lane + 32 * i] = pk[lane + 32 * i];
    }
    __syncwarp();
#pragma unroll
    for (int row2 = 0; row2 < 2; row2++)
#pragma unroll
        for (int cq = 0; cq < 8; cq++) pk[(r0 + row2) * 8 + cq] = plo[row2 * 8 + cq];
    __syncwarp();
    {
        uint32_t* gd = (uint32_t*)(g_bXlo[opar] + doff);
#pragma unroll
        for (int i = 0; i < 16; i++) gd[lane + 32 * i] = pk[lane + 32 * i];
    }
}

// ---------------- X_transformed transpose ------------------------------------
__global__ void xt_kernel(float* __restrict__ out) {
    __shared__ float tile[256][18];
    int base = blockIdx.x * 256;
    int tid = threadIdx.x;
#pragma unroll
    for (int l = 0; l < 17; l++)
        tile[tid][l] = g_xt[(size_t)l * PLANE + base + tid];
    __syncthreads();
    float* o = out + (size_t)base * 17;
    for (int i = tid; i < 256 * 17; i += 256)
        o[i] = tile[i / 17][i % 17];
}

// ---------------- reconstruct + classify + softmax ----------------------------
__global__ __launch_bounds__(128) void classify_kernel(
    const float* __restrict__ Wc, const float* __restrict__ bc,
    float* __restrict__ out, int off_log)
{
    __shared__ float sU[1024], sS[256], sV[1024], sT[1024];
    __shared__ float sZ[4096];
    __shared__ float red[10 * 136];
    __shared__ float slog[10];

    int b = blockIdx.x, tid = threadIdx.x;
    const float* base = g_xt + (size_t)16 * PLANE + (size_t)b * 3 * 1024;

    for (int i = tid; i < 1024; i += 128) { sU[i] = base[i]; sV[i] = base[2048 + i]; }
    for (int i = tid; i < 256; i += 128) sS[i] = base[1024 + i];
    __syncthreads();

    for (int e = tid; e < 1024; e += 128) {
        int r = e >> 4, c = e & 15;
        float sum = 0.f;
#pragma unroll
        for (int k = 0; k < 16; k++) sum += sU[r * 16 + k] * sS[k * 16 + c];
        sT[e] = sum;
    }
    __syncthreads();

    for (int e = tid; e < 4096; e += 128) {
        int r = e >> 6, qn = e & 63;
        float sum = 0.f;
#pragma unroll
        for (int c = 0; c < 16; c++) sum += sT[r * 16 + c] * sV[qn * 16 + c];
        sZ[e] = sum;
    }
    __syncthreads();

    float acc[10];
#pragma unroll
    for (int n = 0; n < 10; n++) acc[n] = 0.f;
    for (int e = tid; e < 4096; e += 128) {
        float z = sZ[e];
#pragma unroll
        for (int n = 0; n < 10; n++) acc[n] += z * Wc[n * 4096 + e];
    }
#pragma unroll
    for (int n = 0; n < 10; n++) red[n * 136 + tid] = acc[n];
    __syncthreads();
    if (tid < 10) {
        float s = bc[tid];
        for (int j = 0; j < 128; j++) s += red[tid * 136 + j];
        slog[tid] = s;
    }
    __syncthreads();
    if (tid == 0) {
        float mx = slog[0];
        for (int n = 1; n < 10; n++) mx = fmaxf(mx, slog[n]);
        float ex[10]; float se = 0.f;
        for (int n = 0; n < 10; n++) { ex[n] = expf(slog[n] - mx); se += ex[n]; }
        float inv = 1.f / se;
        for (int n = 0; n < 10; n++) {
            out[b * 10 + n] = ex[n] * inv;
            if (off_log >= 0) out[off_log + b * 10 + n] = slog[n];
        }
    }
}

// ---------------- launch ------------------------------------------------------
extern "C" void kernel_launch(void* const* d_in, const int* in_sizes, int n_in,
                              void* d_out, int out_size) {
    const float* X  = (const float*)d_in[0];
    const float* h  = (const float*)d_in[1];
    const float* W0 = (const float*)d_in[2];
    const float* Ws = (const float*)d_in[3];
    const float* bs = (const float*)d_in[4];
    const float* Wc = (const float*)d_in[5];
    const float* bc = (const float*)d_in[6];
    float* out = (float*)d_out;

    int off_log = -1, off_xt = -1;
    if (out_size >= 10240 + 10240 + 53477376) { off_log = 10240; off_xt = 20480; }
    else if (out_size == 10240 + 53477376)    { off_xt = 10240; }
    else if (out_size >= 20480)               { off_log = 10240; }

    cudaFuncSetAttribute(tgemm_kernel, cudaFuncAttributeMaxDynamicSharedMemorySize,
                         SMEM_TOTAL_G);

    wconv_kernel<<<WELEMS / 256, 256>>>(W0, Ws);
    prep_kernel<<<PLANE / 256, 256>>>(X);

    tgemm_kernel<<<192, 256, SMEM_TOTAL_G>>>(nullptr, h, 0);
    polar_kernel<<<512, 128>>>(0, 22, 1);
    for (int l = 1; l <= 16; l++) {
        tgemm_kernel<<<192, 256, SMEM_TOTAL_G>>>(bs + (size_t)(l - 1) * 1024, h, l);
        polar_kernel<<<512, 128>>>(l, 13, (l + 1) & 1);
    }

    if (off_xt >= 0)
        xt_kernel<<<PLANE / 256, 256>>>(out + off_xt);
    classify_kernel<<<1024, 128>>>(Wc, bc, out, off_log);
}

// round 5
// speedup vs baseline: 1.6872x; 1.3418x over previous
#include <cuda_runtime.h>
#include <cuda_fp16.h>
#include <math.h>
#include <stdint.h>

#define PLANE 3145728            // 3072 * 1024
#define WELEMS 17825792          // 17 * 1024 * 1024

// ---------------- device scratch --------------------------------------------
__device__ float g_Y[PLANE];                 // pre-projection Y of current layer
__device__ float g_xt[17 * PLANE];           // xs[l] planes (fp32)
__device__ __half g_hXhi[2][PLANE];          // ping-pong split-fp16 X
__device__ __half g_hXlo[2][PLANE];
__device__ __half g_hW[WELEMS];              // fp16 weights (W0 at 0, Ws at 1..16)

// ---------------- helpers -----------------------------------------------------
static __device__ __forceinline__ uint32_t smem_u32(const void* p) {
    return (uint32_t)__cvta_generic_to_shared(p);
}
static __device__ __forceinline__ void ldsm4(uint32_t* r, uint32_t addr) {
    asm volatile("ldmatrix.sync.aligned.m8n8.x4.shared.b16 {%0,%1,%2,%3}, [%4];"
        : "=r"(r[0]), "=r"(r[1]), "=r"(r[2]), "=r"(r[3]) : "r"(addr));
}
static __device__ __forceinline__ void mma16816(float* c, const uint32_t* a,
                                                uint32_t b0, uint32_t b1) {
    asm volatile("mma.sync.aligned.m16n8k16.row.col.f32.f16.f16.f32 "
        "{%0,%1,%2,%3}, {%4,%5,%6,%7}, {%8,%9}, {%0,%1,%2,%3};"
        : "+f"(c[0]), "+f"(c[1]), "+f"(c[2]), "+f"(c[3])
        : "r"(a[0]), "r"(a[1]), "r"(a[2]), "r"(a[3]), "r"(b0), "r"(b1));
}

// ---------------- weight conversion (fp16, single copy) ----------------------
__global__ void wconv_kernel(const float* __restrict__ W0, const float* __restrict__ Ws) {
    size_t i = (size_t)blockIdx.x * 256 + threadIdx.x;
    if (i >= (size_t)WELEMS) return;
    float v = (i < 1048576) ? W0[i] : Ws[i - 1048576];
    g_hW[i] = __float2half_rn(v);
}

// ---------------- prep: split-fp16 of input (ch2 transposed) -----------------
__global__ void prep_kernel(const float* __restrict__ Xin) {
    int idx = blockIdx.x * 256 + threadIdx.x;
    if (idx >= PLANE) return;
    int d  = idx & 1023;
    int bc = idx >> 10;
    int c  = bc % 3;
    float v;
    if (c == 2) {
        int b = bc / 3;
        int dim = d >> 4, k = d & 15;
        v = Xin[((size_t)(b * 3 + 2)) * 1024 + k * 64 + dim];
    } else {
        v = Xin[idx];
    }
    __half h = __float2half_rn(v);
    g_hXhi[0][idx] = h;
    g_hXlo[0][idx] = __float2half_rn(v - __half2float(h));
}

// ---------------- split-fp16 mma.sync GEMM + fused epilogue ------------------
// D[m,n] = sum_d A[m,d]*W[n,d] via 2 fp16 products ((Ah+Al)*Bh = A*Bh exactly).
// Tile 128x128, K-chunk 32, 2-stage cp.async pipeline, 8 warps (2M x 4N).
#define MAT_STRIDE_B 80                  // bytes per smem row (pad, conflict-free)
#define MAT_BYTES (128 * MAT_STRIDE_B)   // 10240
#define STAGE_BYTES (3 * MAT_BYTES)      // 30720
#define SMEM_TOTAL_G (2 * STAGE_BYTES)   // 61440

__global__ __launch_bounds__(256, 2) void tgemm_kernel(
    const float* __restrict__ bias, const float* __restrict__ hp, int layer)
{
    extern __shared__ __align__(16) char smem[];
    uint32_t sb = smem_u32(smem);

    int tid = threadIdx.x;
    int wid = tid >> 5, lane = tid & 31;
    int bx = blockIdx.x;
    int m0 = (bx >> 3) * 128;
    int n0 = (bx & 7) * 128;

    int par = layer & 1;
    const __half* srcs[3];
    srcs[0] = g_hXhi[par] + (size_t)m0 * 1024;
    srcs[1] = g_hXlo[par] + (size_t)m0 * 1024;
    srcs[2] = g_hW + (size_t)layer * 1048576 + (size_t)n0 * 1024;

    float acc[4][4][4];
#pragma unroll
    for (int i = 0; i < 4; i++)
#pragma unroll
        for (int j = 0; j < 4; j++)
#pragma unroll
            for (int k = 0; k < 4; k++) acc[i][j][k] = 0.f;

    auto issue = [&](int c, int st) {
#pragma unroll
        for (int u = 0; u < 6; u++) {
            int unit = tid + u * 256;        // 0..1535
            int mat = unit >> 9;
            int s = unit & 511;
            int row = s >> 2, seg = s & 3;
            uint32_t dst = sb + st * STAGE_BYTES + mat * MAT_BYTES +
                           row * MAT_STRIDE_B + seg * 16;
            const __half* gp = srcs[mat] + (size_t)row * 1024 + c * 32 + seg * 8;
            asm volatile("cp.async.cg.shared.global [%0], [%1], 16;"
                :: "r"(dst), "l"(gp));
        }
        asm volatile("cp.async.commit_group;" ::: "memory");
    };

    issue(0, 0);

    int mw = (wid >> 2) * 64, nw = (wid & 3) * 32;
    int lrow = (lane & 7) + ((lane >> 3) & 1) * 8;
    int lcolB = ((lane >> 4) * 8) * 2;   // byte offset of ldmatrix col

    for (int c = 0; c < 32; c++) {
        int st = c & 1;
        if (c + 1 < 32) {
            issue(c + 1, st ^ 1);
            asm volatile("cp.async.wait_group 1;" ::: "memory");
        } else {
            asm volatile("cp.async.wait_group 0;" ::: "memory");
        }
        __syncthreads();

        uint32_t base = sb + st * STAGE_BYTES;
#pragma unroll
        for (int ks = 0; ks < 2; ks++) {
            int colb = ks * 32 + lcolB;
            uint32_t bh[2][4];
#pragma unroll
            for (int nb = 0; nb < 2; nb++)
                ldsm4(bh[nb], base + 2 * MAT_BYTES +
                              (nw + nb * 16 + lrow) * MAT_STRIDE_B + colb);
#pragma unroll
            for (int ma = 0; ma < 4; ma++) {
                uint32_t ah[4], al[4];
                uint32_t aaddr = base + (mw + ma * 16 + lrow) * MAT_STRIDE_B + colb;
                ldsm4(ah, aaddr);
                ldsm4(al, aaddr + MAT_BYTES);
#pragma unroll
                for (int na = 0; na < 4; na++) {
                    int nb = na >> 1, hi = na & 1;
                    uint32_t b0 = bh[nb][hi], b1 = bh[nb][2 + hi];
                    mma16816(acc[ma][na], ah, b0, b1);
                    mma16816(acc[ma][na], al, b0, b1);
                }
            }
        }
        __syncthreads();
    }

    // ---- fused epilogue from register fragments
    float hv = 0.f;
    const float* Xprev = nullptr;
    if (layer > 0) { hv = *hp; Xprev = g_xt + (size_t)(layer - 1) * PLANE; }
    float* PL = g_xt + (size_t)layer * PLANE;
    int opar = (layer + 1) & 1;
    int g = lane >> 2, t2 = (lane & 3) * 2;

#pragma unroll
    for (int ma = 0; ma < 4; ma++) {
#pragma unroll
        for (int na = 0; na < 4; na++) {
            int n = n0 + nw + na * 8 + t2;
            float2 b2 = make_float2(0.f, 0.f);
            if (layer > 0) b2 = *(const float2*)(bias + n);
#pragma unroll
            for (int hh = 0; hh < 2; hh++) {
                int m = m0 + mw + ma * 16 + g + hh * 8;
                float cx = acc[ma][na][hh * 2], cy = acc[ma][na][hh * 2 + 1];
                float2 y;
                if (layer > 0) {
                    float2 xo = *(const float2*)(Xprev + (size_t)m * 1024 + n);
                    y.x = xo.x + hv * fmaxf(cx + b2.x, 0.f);
                    y.y = xo.y + hv * fmaxf(cy + b2.y, 0.f);
                } else {
                    y.x = cx; y.y = cy;
                }
                *(float2*)(g_Y + (size_t)m * 1024 + n) = y;
                if (m % 3 == 1) {
                    *(float2*)(PL + (size_t)m * 1024 + n) = y;
                    __half hx = __float2half_rn(y.x);
                    __half hy = __float2half_rn(y.y);
                    __half2 h2; h2.x = hx; h2.y = hy;
                    *(__half2*)(&g_hXhi[opar][(size_t)m * 1024 + n]) = h2;
                    __half2 l2;
                    l2.x = __float2half_rn(y.x - __half2float(hx));
                    l2.y = __float2half_rn(y.y - __half2float(hy));
                    *(__half2*)(&g_hXlo[opar][(size_t)m * 1024 + n]) = l2;
                }
            }
        }
    }
}

// ---------------- polar projection (tuned Newton-Schulz on 16x16 Gram) -------
// Coupled iteration Y<-Y*T, Z<-T*Z with T = a*I + b*(Z*Y).
// Aggressive steps (2.4,-1.4) grow small singular values 2.4x/step (overshoot
// capped at 1.21 < positivity bound 1.31); classic (1.5,-0.5) finishes quadratically.
#define PNW 4
__global__ __launch_bounds__(128) void polar_kernel(int plane, int nagg, int nclassic,
                                                    int opar) {
    __shared__ float AsP[PNW][16][68];
    __shared__ float MsP[PNW][3][16][20];

    int w = threadIdx.x >> 5, lane = threadIdx.x & 31;
    int idx = blockIdx.x * PNW + w;
    int b = idx >> 1, ch = (idx & 1) * 2;

    const float* src = g_Y + (size_t)(b * 3 + ch) * 1024;
    size_t doff = (size_t)(b * 3 + ch) * 1024;
    float* dst = g_xt + (size_t)plane * PLANE + doff;

    float (*A)[68]  = AsP[w];
    float (*Ym)[20] = MsP[w][0];
    float (*Zm)[20] = MsP[w][1];
    float (*Tm)[20] = MsP[w][2];

    int r0 = lane * 2;
#pragma unroll
    for (int qq = 0; qq < 4; qq++) {
        float4 v0 = *(const float4*)(src + r0 * 16 + qq * 4);
        float4 v1 = *(const float4*)(src + (r0 + 1) * 16 + qq * 4);
        A[qq * 4 + 0][r0] = v0.x; A[qq * 4 + 1][r0] = v0.y;
        A[qq * 4 + 2][r0] = v0.z; A[qq * 4 + 3][r0] = v0.w;
        A[qq * 4 + 0][r0 + 1] = v1.x; A[qq * 4 + 1][r0 + 1] = v1.y;
        A[qq * 4 + 2][r0 + 1] = v1.z; A[qq * 4 + 3][r0 + 1] = v1.w;
    }
    __syncwarp();

    int i0 = (lane >> 2) * 2, j0 = (lane & 3) * 4;
    float g0[4] = {0, 0, 0, 0}, g1[4] = {0, 0, 0, 0};
#pragma unroll
    for (int r = 0; r < 64; r += 4) {
        float4 a0 = *(const float4*)&A[i0][r];
        float4 a1 = *(const float4*)&A[i0 + 1][r];
#pragma unroll
        for (int t = 0; t < 4; t++) {
            float4 aj = *(const float4*)&A[j0 + t][r];
            g0[t] += a0.x * aj.x + a0.y * aj.y + a0.z * aj.z + a0.w * aj.w;
            g1[t] += a1.x * aj.x + a1.y * aj.y + a1.z * aj.z + a1.w * aj.w;
        }
    }
    *(float4*)&Ym[i0][j0]     = make_float4(g0[0], g0[1], g0[2], g0[3]);
    *(float4*)&Ym[i0 + 1][j0] = make_float4(g1[0], g1[1], g1[2], g1[3]);
    __syncwarp();

    float rs = 0.f;
    if (lane < 16) {
#pragma unroll
        for (int j = 0; j < 16; j++) rs += fabsf(Ym[lane][j]);
    }
#pragma unroll
    for (int off = 16; off; off >>= 1)
        rs = fmaxf(rs, __shfl_xor_sync(0xffffffffu, rs, off));
    float invs = 1.0f / rs;

#pragma unroll
    for (int t = 0; t < 4; t++) { g0[t] *= invs; g1[t] *= invs; }
    *(float4*)&Ym[i0][j0]     = make_float4(g0[0], g0[1], g0[2], g0[3]);
    *(float4*)&Ym[i0 + 1][j0] = make_float4(g1[0], g1[1], g1[2], g1[3]);
    *(float4*)&Zm[i0][j0] = make_float4(i0 == j0 ? 1.f : 0.f, i0 == j0 + 1 ? 1.f : 0.f,
                                        i0 == j0 + 2 ? 1.f : 0.f, i0 == j0 + 3 ? 1.f : 0.f);
    *(float4*)&Zm[i0 + 1][j0] = make_float4(i0 + 1 == j0 ? 1.f : 0.f, i0 + 1 == j0 + 1 ? 1.f : 0.f,
                                            i0 + 1 == j0 + 2 ? 1.f : 0.f, i0 + 1 == j0 + 3 ? 1.f : 0.f);
    __syncwarp();

    int ntot = nagg + nclassic;
    for (int it = 0; it < ntot; it++) {
        float ca = (it < nagg) ? 2.4f : 1.5f;
        float cb = (it < nagg) ? -1.4f : -0.5f;
        float t0[4] = {0, 0, 0, 0}, t1[4] = {0, 0, 0, 0};
#pragma unroll
        for (int k = 0; k < 16; k++) {
            float z0 = Zm[i0][k], z1 = Zm[i0 + 1][k];
            float4 y4 = *(const float4*)&Ym[k][j0];
            t0[0] += z0 * y4.x; t0[1] += z0 * y4.y; t0[2] += z0 * y4.z; t0[3] += z0 * y4.w;
            t1[0] += z1 * y4.x; t1[1] += z1 * y4.y; t1[2] += z1 * y4.z; t1[3] += z1 * y4.w;
        }
#pragma unroll
        for (int t = 0; t < 4; t++) {
            t0[t] = ((i0     == j0 + t) ? ca : 0.f) + cb * t0[t];
            t1[t] = ((i0 + 1 == j0 + t) ? ca : 0.f) + cb * t1[t];
        }
        *(float4*)&Tm[i0][j0]     = make_float4(t0[0], t0[1], t0[2], t0[3]);
        *(float4*)&Tm[i0 + 1][j0] = make_float4(t1[0], t1[1], t1[2], t1[3]);
        __syncwarp();

        float yn0[4] = {0, 0, 0, 0}, yn1[4] = {0, 0, 0, 0};
        float zn0[4] = {0, 0, 0, 0}, zn1[4] = {0, 0, 0, 0};
#pragma unroll
        for (int k = 0; k < 16; k++) {
            float4 t4 = *(const float4*)&Tm[k][j0];
            float ya = Ym[i0][k], yb = Ym[i0 + 1][k];
            yn0[0] += ya * t4.x; yn0[1] += ya * t4.y; yn0[2] += ya * t4.z; yn0[3] += ya * t4.w;
            yn1[0] += yb * t4.x; yn1[1] += yb * t4.y; yn1[2] += yb * t4.z; yn1[3] += yb * t4.w;
            float4 z4 = *(const float4*)&Zm[k][j0];
            float ta = Tm[i0][k], tb = Tm[i0 + 1][k];
            zn0[0] += ta * z4.x; zn0[1] += ta * z4.y; zn0[2] += ta * z4.z; zn0[3] += ta * z4.w;
            zn1[0] += tb * z4.x; zn1[1] += tb * z4.y; zn1[2] += tb * z4.z; zn1[3] += tb * z4.w;
        }
        __syncwarp();
        *(float4*)&Ym[i0][j0]     = make_float4(yn0[0], yn0[1], yn0[2], yn0[3]);
        *(float4*)&Ym[i0 + 1][j0] = make_float4(yn1[0], yn1[1], yn1[2], yn1[3]);
        *(float4*)&Zm[i0][j0]     = make_float4(zn0[0], zn0[1], zn0[2], zn0[3]);
        *(float4*)&Zm[i0 + 1][j0] = make_float4(zn1[0], zn1[1], zn1[2], zn1[3]);
        __syncwarp();
    }

    float isq = rsqrtf(rs);
    float u0[16], u1[16];
#pragma unroll
    for (int c = 0; c < 16; c++) { u0[c] = 0.f; u1[c] = 0.f; }
#pragma unroll
    for (int k = 0; k < 16; k++) {
        float a0 = A[k][r0], a1 = A[k][r0 + 1];
#pragma unroll
        for (int cq = 0; cq < 4; cq++) {
            float4 z4 = *(const float4*)&Zm[k][cq * 4];
            u0[cq * 4 + 0] += a0 * z4.x; u0[cq * 4 + 1] += a0 * z4.y;
            u0[cq * 4 + 2] += a0 * z4.z; u0[cq * 4 + 3] += a0 * z4.w;
            u1[cq * 4 + 0] += a1 * z4.x; u1[cq * 4 + 1] += a1 * z4.y;
            u1[cq * 4 + 2] += a1 * z4.z; u1[cq * 4 + 3] += a1 * z4.w;
        }
    }
#pragma unroll
    for (int c = 0; c < 16; c++) { u0[c] *= isq; u1[c] *= isq; }

    // fp32 U out
#pragma unroll
    for (int cq = 0; cq < 4; cq++) {
        *(float4*)(dst + r0 * 16 + cq * 4) =
            make_float4(u0[cq * 4], u0[cq * 4 + 1], u0[cq * 4 + 2], u0[cq * 4 + 3]);
        *(float4*)(dst + (r0 + 1) * 16 + cq * 4) =
            make_float4(u1[cq * 4], u1[cq * 4 + 1], u1[cq * 4 + 2], u1[cq * 4 + 3]);
    }

    // split-fp16 out: pack via smem for coalesced writes
    uint32_t phi[16], plo[16];
#pragma unroll
    for (int row2 = 0; row2 < 2; row2++) {
        float* u = row2 ? u1 : u0;
#pragma unroll
        for (int cq = 0; cq < 8; cq++) {
            float a = u[2 * cq], bb = u[2 * cq + 1];
            __half ha = __float2half_rn(a);
            __half hb = __float2half_rn(bb);
            __half2 hp2; hp2.x = ha; hp2.y = hb;
            phi[row2 * 8 + cq] = *(uint32_t*)&hp2;
            __half2 lp2;
            lp2.x = __float2half_rn(a - __half2float(ha));
            lp2.y = __float2half_rn(bb - __half2float(hb));
            plo[row2 * 8 + cq] = *(uint32_t*)&lp2;
        }
    }
    __syncwarp();
    uint32_t* pk = (uint32_t*)&A[0][0];
#pragma unroll
    for (int row2 = 0; row2 < 2; row2++)
#pragma unroll
        for (int cq = 0; cq < 8; cq++) pk[(r0 + row2) * 8 + cq] = phi[row2 * 8 + cq];
    __syncwarp();
    {
        uint32_t* gd = (uint32_t*)(g_hXhi[opar] + doff);
#pragma unroll
        for (int i = 0; i < 16; i++) gd[lane + 32 * i] = pk[lane + 32 * i];
    }
    __syncwarp();
#pragma unroll
    for (int row2 = 0; row2 < 2; row2++)
#pragma unroll
        for (int cq = 0; cq < 8; cq++) pk[(r0 + row2) * 8 + cq] = plo[row2 * 8 + cq];
    __syncwarp();
    {
        uint32_t* gd = (uint32_t*)(g_hXlo[opar] + doff);
#pragma unroll
        for (int i = 0; i < 16; i++) gd[lane + 32 * i] = pk[lane + 32 * i];
    }
}

// ---------------- X_transformed transpose ------------------------------------
__global__ void xt_kernel(float* __restrict__ out) {
    __shared__ float tile[256][18];
    int base = blockIdx.x * 256;
    int tid = threadIdx.x;
#pragma unroll
    for (int l = 0; l < 17; l++)
        tile[tid][l] = g_xt[(size_t)l * PLANE + base + tid];
    __syncthreads();
    float* o = out + (size_t)base * 17;
    for (int i = tid; i < 256 * 17; i += 256)
        o[i] = tile[i / 17][i % 17];
}

// ---------------- reconstruct + classify + softmax ----------------------------
__global__ __launch_bounds__(128) void classify_kernel(
    const float* __restrict__ Wc, const float* __restrict__ bc,
    float* __restrict__ out, int off_log)
{
    __shared__ float sU[1024], sS[256], sV[1024], sT[1024];
    __shared__ float sZ[4096];
    __shared__ float red[10 * 136];
    __shared__ float slog[10];

    int b = blockIdx.x, tid = threadIdx.x;
    const float* base = g_xt + (size_t)16 * PLANE + (size_t)b * 3 * 1024;

    for (int i = tid; i < 1024; i += 128) { sU[i] = base[i]; sV[i] = base[2048 + i]; }
    for (int i = tid; i < 256; i += 128) sS[i] = base[1024 + i];
    __syncthreads();

    for (int e = tid; e < 1024; e += 128) {
        int r = e >> 4, c = e & 15;
        float sum = 0.f;
#pragma unroll
        for (int k = 0; k < 16; k++) sum += sU[r * 16 + k] * sS[k * 16 + c];
        sT[e] = sum;
    }
    __syncthreads();

    for (int e = tid; e < 4096; e += 128) {
        int r = e >> 6, qn = e & 63;
        float sum = 0.f;
#pragma unroll
        for (int c = 0; c < 16; c++) sum += sT[r * 16 + c] * sV[qn * 16 + c];
        sZ[e] = sum;
    }
    __syncthreads();

    float acc[10];
#pragma unroll
    for (int n = 0; n < 10; n++) acc[n] = 0.f;
    for (int e = tid; e < 4096; e += 128) {
        float z = sZ[e];
#pragma unroll
        for (int n = 0; n < 10; n++) acc[n] += z * Wc[n * 4096 + e];
    }
#pragma unroll
    for (int n = 0; n < 10; n++) red[n * 136 + tid] = acc[n];
    __syncthreads();
    if (tid < 10) {
        float s = bc[tid];
        for (int j = 0; j < 128; j++) s += red[tid * 136 + j];
        slog[tid] = s;
    }
    __syncthreads();
    if (tid == 0) {
        float mx = slog[0];
        for (int n = 1; n < 10; n++) mx = fmaxf(mx, slog[n]);
        float ex[10]; float se = 0.f;
        for (int n = 0; n < 10; n++) { ex[n] = expf(slog[n] - mx); se += ex[n]; }
        float inv = 1.f / se;
        for (int n = 0; n < 10; n++) {
            out[b * 10 + n] = ex[n] * inv;
            if (off_log >= 0) out[off_log + b * 10 + n] = slog[n];
        }
    }
}

// ---------------- launch ------------------------------------------------------
extern "C" void kernel_launch(void* const* d_in, const int* in_sizes, int n_in,
                              void* d_out, int out_size) {
    const float* X  = (const float*)d_in[0];
    const float* h  = (const float*)d_in[1];
    const float* W0 = (const float*)d_in[2];
    const float* Ws = (const float*)d_in[3];
    const float* bs = (const float*)d_in[4];
    const float* Wc = (const float*)d_in[5];
    const float* bc = (const float*)d_in[6];
    float* out = (float*)d_out;

    int off_log = -1, off_xt = -1;
    if (out_size >= 10240 + 10240 + 53477376) { off_log = 10240; off_xt = 20480; }
    else if (out_size == 10240 + 53477376)    { off_xt = 10240; }
    else if (out_size >= 20480)               { off_log = 10240; }

    cudaFuncSetAttribute(tgemm_kernel, cudaFuncAttributeMaxDynamicSharedMemorySize,
                         SMEM_TOTAL_G);

    wconv_kernel<<<WELEMS / 256, 256>>>(W0, Ws);
    prep_kernel<<<PLANE / 256, 256>>>(X);

    tgemm_kernel<<<192, 256, SMEM_TOTAL_G>>>(nullptr, h, 0);
    polar_kernel<<<512, 128>>>(0, 4, 6, 1);       // layer 0: 4 aggressive + 6 classic
    for (int l = 1; l <= 16; l++) {
        tgemm_kernel<<<192, 256, SMEM_TOTAL_G>>>(bs + (size_t)(l - 1) * 1024, h, l);
        polar_kernel<<<512, 128>>>(l, 0, 6, (l + 1) & 1);   // near-orthogonal: 6 classic
    }

    if (off_xt >= 0)
        xt_kernel<<<PLANE / 256, 256>>>(out + off_xt);
    classify_kernel<<<1024, 128>>>(Wc, bc, out, off_log);
}

// round 6
// speedup vs baseline: 2.3141x; 1.3715x over previous
#include <cuda_runtime.h>
#include <cuda_fp16.h>
#include <math.h>
#include <stdint.h>

#define PLANE 3145728            // 3072 * 1024
#define WELEMS 17825792          // 17 * 1024 * 1024

// ---------------- device scratch --------------------------------------------
__device__ float g_Y[PLANE];                 // pre-projection Y of current layer
__device__ float g_xt[17 * PLANE];           // xs[l] planes (fp32)
__device__ __half g_hX[2][PLANE];            // ping-pong fp16 X
__device__ __half g_hW[WELEMS];              // fp16 weights (W0 at 0, Ws at 1..16)

// ---------------- helpers -----------------------------------------------------
static __device__ __forceinline__ uint32_t smem_u32(const void* p) {
    return (uint32_t)__cvta_generic_to_shared(p);
}
static __device__ __forceinline__ void ldsm4(uint32_t* r, uint32_t addr) {
    asm volatile("ldmatrix.sync.aligned.m8n8.x4.shared.b16 {%0,%1,%2,%3}, [%4];"
        : "=r"(r[0]), "=r"(r[1]), "=r"(r[2]), "=r"(r[3]) : "r"(addr));
}
static __device__ __forceinline__ void mma16816(float* c, const uint32_t* a,
                                                uint32_t b0, uint32_t b1) {
    asm volatile("mma.sync.aligned.m16n8k16.row.col.f32.f16.f16.f32 "
        "{%0,%1,%2,%3}, {%4,%5,%6,%7}, {%8,%9}, {%0,%1,%2,%3};"
        : "+f"(c[0]), "+f"(c[1]), "+f"(c[2]), "+f"(c[3])
        : "r"(a[0]), "r"(a[1]), "r"(a[2]), "r"(a[3]), "r"(b0), "r"(b1));
}

// ---------------- weight conversion (fp16) -----------------------------------
__global__ void wconv_kernel(const float* __restrict__ W0, const float* __restrict__ Ws) {
    size_t i = (size_t)blockIdx.x * 256 + threadIdx.x;
    if (i >= (size_t)WELEMS) return;
    float v = (i < 1048576) ? W0[i] : Ws[i - 1048576];
    g_hW[i] = __float2half_rn(v);
}

// ---------------- prep: fp16 of input (ch2 transposed) -----------------------
__global__ void prep_kernel(const float* __restrict__ Xin) {
    int idx = blockIdx.x * 256 + threadIdx.x;
    if (idx >= PLANE) return;
    int d  = idx & 1023;
    int bc = idx >> 10;
    int c  = bc % 3;
    float v;
    if (c == 2) {
        int b = bc / 3;
        int dim = d >> 4, k = d & 15;
        v = Xin[((size_t)(b * 3 + 2)) * 1024 + k * 64 + dim];
    } else {
        v = Xin[idx];
    }
    g_hX[0][idx] = __float2half_rn(v);
}

// ---------------- fp16 mma.sync GEMM + fused epilogue ------------------------
// D[m,n] = sum_d A[m,d]*W[n,d], single fp16 product.
// Tile 128x128, K-chunk 32, 3-stage cp.async pipeline, 8 warps (2M x 4N).
#define MAT_STRIDE_B 80                  // bytes per smem row (pad, conflict-free)
#define MAT_BYTES (128 * MAT_STRIDE_B)   // 10240
#define STAGE_BYTES (2 * MAT_BYTES)      // 20480
#define SMEM_TOTAL_G (3 * STAGE_BYTES)   // 61440

__global__ __launch_bounds__(256, 2) void tgemm_kernel(
    const float* __restrict__ bias, const float* __restrict__ hp, int layer)
{
    extern __shared__ __align__(16) char smem[];
    uint32_t sb = smem_u32(smem);

    int tid = threadIdx.x;
    int wid = tid >> 5, lane = tid & 31;
    int bx = blockIdx.x;
    int m0 = (bx >> 3) * 128;
    int n0 = (bx & 7) * 128;

    int par = layer & 1;
    const __half* srcs[2];
    srcs[0] = g_hX[par] + (size_t)m0 * 1024;
    srcs[1] = g_hW + (size_t)layer * 1048576 + (size_t)n0 * 1024;

    float acc[4][4][4];
#pragma unroll
    for (int i = 0; i < 4; i++)
#pragma unroll
        for (int j = 0; j < 4; j++)
#pragma unroll
            for (int k = 0; k < 4; k++) acc[i][j][k] = 0.f;

    auto issue = [&](int c, int st) {
#pragma unroll
        for (int u = 0; u < 4; u++) {
            int unit = tid + u * 256;        // 0..1023
            int mat = unit >> 9;
            int s = unit & 511;
            int row = s >> 2, seg = s & 3;
            uint32_t dst = sb + st * STAGE_BYTES + mat * MAT_BYTES +
                           row * MAT_STRIDE_B + seg * 16;
            const __half* gp = srcs[mat] + (size_t)row * 1024 + c * 32 + seg * 8;
            asm volatile("cp.async.cg.shared.global [%0], [%1], 16;"
                :: "r"(dst), "l"(gp));
        }
        asm volatile("cp.async.commit_group;" ::: "memory");
    };

    issue(0, 0);
    issue(1, 1);

    int mw = (wid >> 2) * 64, nw = (wid & 3) * 32;
    int lrow = (lane & 7) + ((lane >> 3) & 1) * 8;
    int lcolB = ((lane >> 4) * 8) * 2;   // byte offset of ldmatrix col

    for (int c = 0; c < 32; c++) {
        int st = c % 3;
        if (c + 2 < 32) {
            issue(c + 2, (c + 2) % 3);
            asm volatile("cp.async.wait_group 2;" ::: "memory");
        } else if (c + 1 < 32) {
            asm volatile("cp.async.wait_group 1;" ::: "memory");
        } else {
            asm volatile("cp.async.wait_group 0;" ::: "memory");
        }
        __syncthreads();

        uint32_t base = sb + st * STAGE_BYTES;
#pragma unroll
        for (int ks = 0; ks < 2; ks++) {
            int colb = ks * 32 + lcolB;
            uint32_t bh[2][4];
#pragma unroll
            for (int nb = 0; nb < 2; nb++)
                ldsm4(bh[nb], base + MAT_BYTES +
                              (nw + nb * 16 + lrow) * MAT_STRIDE_B + colb);
#pragma unroll
            for (int ma = 0; ma < 4; ma++) {
                uint32_t ah[4];
                ldsm4(ah, base + (mw + ma * 16 + lrow) * MAT_STRIDE_B + colb);
#pragma unroll
                for (int na = 0; na < 4; na++) {
                    int nb = na >> 1, hi = na & 1;
                    mma16816(acc[ma][na], ah, bh[nb][hi], bh[nb][2 + hi]);
                }
            }
        }
        __syncthreads();
    }

    // ---- fused epilogue from register fragments
    float hv = 0.f;
    const float* Xprev = nullptr;
    if (layer > 0) { hv = *hp; Xprev = g_xt + (size_t)(layer - 1) * PLANE; }
    float* PL = g_xt + (size_t)layer * PLANE;
    int opar = (layer + 1) & 1;
    int g = lane >> 2, t2 = (lane & 3) * 2;

#pragma unroll
    for (int ma = 0; ma < 4; ma++) {
#pragma unroll
        for (int na = 0; na < 4; na++) {
            int n = n0 + nw + na * 8 + t2;
            float2 b2 = make_float2(0.f, 0.f);
            if (layer > 0) b2 = *(const float2*)(bias + n);
#pragma unroll
            for (int hh = 0; hh < 2; hh++) {
                int m = m0 + mw + ma * 16 + g + hh * 8;
                float cx = acc[ma][na][hh * 2], cy = acc[ma][na][hh * 2 + 1];
                float2 y;
                if (layer > 0) {
                    float2 xo = *(const float2*)(Xprev + (size_t)m * 1024 + n);
                    y.x = xo.x + hv * fmaxf(cx + b2.x, 0.f);
                    y.y = xo.y + hv * fmaxf(cy + b2.y, 0.f);
                } else {
                    y.x = cx; y.y = cy;
                }
                *(float2*)(g_Y + (size_t)m * 1024 + n) = y;
                if (m % 3 == 1) {
                    *(float2*)(PL + (size_t)m * 1024 + n) = y;
                    __half2 h2;
                    h2.x = __float2half_rn(y.x);
                    h2.y = __float2half_rn(y.y);
                    *(__half2*)(&g_hX[opar][(size_t)m * 1024 + n]) = h2;
                }
            }
        }
    }
}

// ---------------- polar projection (tuned Newton-Schulz on 16x16 Gram) -------
#define PNW 4
__global__ __launch_bounds__(128) void polar_kernel(int plane, int nagg, int nclassic,
                                                    int opar) {
    __shared__ float AsP[PNW][16][68];
    __shared__ float MsP[PNW][3][16][20];

    int w = threadIdx.x >> 5, lane = threadIdx.x & 31;
    int idx = blockIdx.x * PNW + w;
    int b = idx >> 1, ch = (idx & 1) * 2;

    const float* src = g_Y + (size_t)(b * 3 + ch) * 1024;
    size_t doff = (size_t)(b * 3 + ch) * 1024;
    float* dst = g_xt + (size_t)plane * PLANE + doff;

    float (*A)[68]  = AsP[w];
    float (*Ym)[20] = MsP[w][0];
    float (*Zm)[20] = MsP[w][1];
    float (*Tm)[20] = MsP[w][2];

    int r0 = lane * 2;
#pragma unroll
    for (int qq = 0; qq < 4; qq++) {
        float4 v0 = *(const float4*)(src + r0 * 16 + qq * 4);
        float4 v1 = *(const float4*)(src + (r0 + 1) * 16 + qq * 4);
        A[qq * 4 + 0][r0] = v0.x; A[qq * 4 + 1][r0] = v0.y;
        A[qq * 4 + 2][r0] = v0.z; A[qq * 4 + 3][r0] = v0.w;
        A[qq * 4 + 0][r0 + 1] = v1.x; A[qq * 4 + 1][r0 + 1] = v1.y;
        A[qq * 4 + 2][r0 + 1] = v1.z; A[qq * 4 + 3][r0 + 1] = v1.w;
    }
    __syncwarp();

    int i0 = (lane >> 2) * 2, j0 = (lane & 3) * 4;
    float g0[4] = {0, 0, 0, 0}, g1[4] = {0, 0, 0, 0};
#pragma unroll
    for (int r = 0; r < 64; r += 4) {
        float4 a0 = *(const float4*)&A[i0][r];
        float4 a1 = *(const float4*)&A[i0 + 1][r];
#pragma unroll
        for (int t = 0; t < 4; t++) {
            float4 aj = *(const float4*)&A[j0 + t][r];
            g0[t] += a0.x * aj.x + a0.y * aj.y + a0.z * aj.z + a0.w * aj.w;
            g1[t] += a1.x * aj.x + a1.y * aj.y + a1.z * aj.z + a1.w * aj.w;
        }
    }
    *(float4*)&Ym[i0][j0]     = make_float4(g0[0], g0[1], g0[2], g0[3]);
    *(float4*)&Ym[i0 + 1][j0] = make_float4(g1[0], g1[1], g1[2], g1[3]);
    __syncwarp();

    float rs = 0.f;
    if (lane < 16) {
#pragma unroll
        for (int j = 0; j < 16; j++) rs += fabsf(Ym[lane][j]);
    }
#pragma unroll
    for (int off = 16; off; off >>= 1)
        rs = fmaxf(rs, __shfl_xor_sync(0xffffffffu, rs, off));
    float invs = 1.0f / rs;

#pragma unroll
    for (int t = 0; t < 4; t++) { g0[t] *= invs; g1[t] *= invs; }
    *(float4*)&Ym[i0][j0]     = make_float4(g0[0], g0[1], g0[2], g0[3]);
    *(float4*)&Ym[i0 + 1][j0] = make_float4(g1[0], g1[1], g1[2], g1[3]);
    *(float4*)&Zm[i0][j0] = make_float4(i0 == j0 ? 1.f : 0.f, i0 == j0 + 1 ? 1.f : 0.f,
                                        i0 == j0 + 2 ? 1.f : 0.f, i0 == j0 + 3 ? 1.f : 0.f);
    *(float4*)&Zm[i0 + 1][j0] = make_float4(i0 + 1 == j0 ? 1.f : 0.f, i0 + 1 == j0 + 1 ? 1.f : 0.f,
                                            i0 + 1 == j0 + 2 ? 1.f : 0.f, i0 + 1 == j0 + 3 ? 1.f : 0.f);
    __syncwarp();

    int ntot = nagg + nclassic;
    for (int it = 0; it < ntot; it++) {
        float ca = (it < nagg) ? 2.4f : 1.5f;
        float cb = (it < nagg) ? -1.4f : -0.5f;
        float t0[4] = {0, 0, 0, 0}, t1[4] = {0, 0, 0, 0};
#pragma unroll
        for (int k = 0; k < 16; k++) {
            float z0 = Zm[i0][k], z1 = Zm[i0 + 1][k];
            float4 y4 = *(const float4*)&Ym[k][j0];
            t0[0] += z0 * y4.x; t0[1] += z0 * y4.y; t0[2] += z0 * y4.z; t0[3] += z0 * y4.w;
            t1[0] += z1 * y4.x; t1[1] += z1 * y4.y; t1[2] += z1 * y4.z; t1[3] += z1 * y4.w;
        }
#pragma unroll
        for (int t = 0; t < 4; t++) {
            t0[t] = ((i0     == j0 + t) ? ca : 0.f) + cb * t0[t];
            t1[t] = ((i0 + 1 == j0 + t) ? ca : 0.f) + cb * t1[t];
        }
        *(float4*)&Tm[i0][j0]     = make_float4(t0[0], t0[1], t0[2], t0[3]);
        *(float4*)&Tm[i0 + 1][j0] = make_float4(t1[0], t1[1], t1[2], t1[3]);
        __syncwarp();

        float yn0[4] = {0, 0, 0, 0}, yn1[4] = {0, 0, 0, 0};
        float zn0[4] = {0, 0, 0, 0}, zn1[4] = {0, 0, 0, 0};
#pragma unroll
        for (int k = 0; k < 16; k++) {
            float4 t4 = *(const float4*)&Tm[k][j0];
            float ya = Ym[i0][k], yb = Ym[i0 + 1][k];
            yn0[0] += ya * t4.x; yn0[1] += ya * t4.y; yn0[2] += ya * t4.z; yn0[3] += ya * t4.w;
            yn1[0] += yb * t4.x; yn1[1] += yb * t4.y; yn1[2] += yb * t4.z; yn1[3] += yb * t4.w;
            float4 z4 = *(const float4*)&Zm[k][j0];
            float ta = Tm[i0][k], tb = Tm[i0 + 1][k];
            zn0[0] += ta * z4.x; zn0[1] += ta * z4.y; zn0[2] += ta * z4.z; zn0[3] += ta * z4.w;
            zn1[0] += tb * z4.x; zn1[1] += tb * z4.y; zn1[2] += tb * z4.z; zn1[3] += tb * z4.w;
        }
        __syncwarp();
        *(float4*)&Ym[i0][j0]     = make_float4(yn0[0], yn0[1], yn0[2], yn0[3]);
        *(float4*)&Ym[i0 + 1][j0] = make_float4(yn1[0], yn1[1], yn1[2], yn1[3]);
        *(float4*)&Zm[i0][j0]     = make_float4(zn0[0], zn0[1], zn0[2], zn0[3]);
        *(float4*)&Zm[i0 + 1][j0] = make_float4(zn1[0], zn1[1], zn1[2], zn1[3]);
        __syncwarp();
    }

    float isq = rsqrtf(rs);
    float u0[16], u1[16];
#pragma unroll
    for (int c = 0; c < 16; c++) { u0[c] = 0.f; u1[c] = 0.f; }
#pragma unroll
    for (int k = 0; k < 16; k++) {
        float a0 = A[k][r0], a1 = A[k][r0 + 1];
#pragma unroll
        for (int cq = 0; cq < 4; cq++) {
            float4 z4 = *(const float4*)&Zm[k][cq * 4];
            u0[cq * 4 + 0] += a0 * z4.x; u0[cq * 4 + 1] += a0 * z4.y;
            u0[cq * 4 + 2] += a0 * z4.z; u0[cq * 4 + 3] += a0 * z4.w;
            u1[cq * 4 + 0] += a1 * z4.x; u1[cq * 4 + 1] += a1 * z4.y;
            u1[cq * 4 + 2] += a1 * z4.z; u1[cq * 4 + 3] += a1 * z4.w;
        }
    }
#pragma unroll
    for (int c = 0; c < 16; c++) { u0[c] *= isq; u1[c] *= isq; }

    // fp32 U out
#pragma unroll
    for (int cq = 0; cq < 4; cq++) {
        *(float4*)(dst + r0 * 16 + cq * 4) =
            make_float4(u0[cq * 4], u0[cq * 4 + 1], u0[cq * 4 + 2], u0[cq * 4 + 3]);
        *(float4*)(dst + (r0 + 1) * 16 + cq * 4) =
            make_float4(u1[cq * 4], u1[cq * 4 + 1], u1[cq * 4 + 2], u1[cq * 4 + 3]);
    }

    // fp16 out: pack via smem for coalesced writes
    uint32_t phi[16];
#pragma unroll
    for (int row2 = 0; row2 < 2; row2++) {
        float* u = row2 ? u1 : u0;
#pragma unroll
        for (int cq = 0; cq < 8; cq++) {
            __half2 hp2;
            hp2.x = __float2half_rn(u[2 * cq]);
            hp2.y = __float2half_rn(u[2 * cq + 1]);
            phi[row2 * 8 + cq] = *(uint32_t*)&hp2;
        }
    }
    __syncwarp();
    uint32_t* pk = (uint32_t*)&A[0][0];
#pragma unroll
    for (int row2 = 0; row2 < 2; row2++)
#pragma unroll
        for (int cq = 0; cq < 8; cq++) pk[(r0 + row2) * 8 + cq] = phi[row2 * 8 + cq];
    __syncwarp();
    {
        uint32_t* gd = (uint32_t*)(g_hX[opar] + doff);
#pragma unroll
        for (int i = 0; i < 16; i++) gd[lane + 32 * i] = pk[lane + 32 * i];
    }
}

// ---------------- X_transformed transpose ------------------------------------
__global__ void xt_kernel(float* __restrict__ out) {
    __shared__ float tile[256][18];
    int base = blockIdx.x * 256;
    int tid = threadIdx.x;
#pragma unroll
    for (int l = 0; l < 17; l++)
        tile[tid][l] = g_xt[(size_t)l * PLANE + base + tid];
    __syncthreads();
    float* o = out + (size_t)base * 17;
    for (int i = tid; i < 256 * 17; i += 256)
        o[i] = tile[i / 17][i % 17];
}

// ---------------- reconstruct + classify + softmax ----------------------------
__global__ __launch_bounds__(128) void classify_kernel(
    const float* __restrict__ Wc, const float* __restrict__ bc,
    float* __restrict__ out, int off_log)
{
    __shared__ float sU[1024], sS[256], sV[1024], sT[1024];
    __shared__ float sZ[4096];
    __shared__ float red[10 * 136];
    __shared__ float slog[10];

    int b = blockIdx.x, tid = threadIdx.x;
    const float* base = g_xt + (size_t)16 * PLANE + (size_t)b * 3 * 1024;

    for (int i = tid; i < 1024; i += 128) { sU[i] = base[i]; sV[i] = base[2048 + i]; }
    for (int i = tid; i < 256; i += 128) sS[i] = base[1024 + i];
    __syncthreads();

    for (int e = tid; e < 1024; e += 128) {
        int r = e >> 4, c = e & 15;
        float sum = 0.f;
#pragma unroll
        for (int k = 0; k < 16; k++) sum += sU[r * 16 + k] * sS[k * 16 + c];
        sT[e] = sum;
    }
    __syncthreads();

    for (int e = tid; e < 4096; e += 128) {
        int r = e >> 6, qn = e & 63;
        float sum = 0.f;
#pragma unroll
        for (int c = 0; c < 16; c++) sum += sT[r * 16 + c] * sV[qn * 16 + c];
        sZ[e] = sum;
    }
    __syncthreads();

    float acc[10];
#pragma unroll
    for (int n = 0; n < 10; n++) acc[n] = 0.f;
    for (int e = tid; e < 4096; e += 128) {
        float z = sZ[e];
#pragma unroll
        for (int n = 0; n < 10; n++) acc[n] += z * Wc[n * 4096 + e];
    }
#pragma unroll
    for (int n = 0; n < 10; n++) red[n * 136 + tid] = acc[n];
    __syncthreads();
    if (tid < 10) {
        float s = bc[tid];
        for (int j = 0; j < 128; j++) s += red[tid * 136 + j];
        slog[tid] = s;
    }
    __syncthreads();
    if (tid == 0) {
        float mx = slog[0];
        for (int n = 1; n < 10; n++) mx = fmaxf(mx, slog[n]);
        float ex[10]; float se = 0.f;
        for (int n = 0; n < 10; n++) { ex[n] = expf(slog[n] - mx); se += ex[n]; }
        float inv = 1.f / se;
        for (int n = 0; n < 10; n++) {
            out[b * 10 + n] = ex[n] * inv;
            if (off_log >= 0) out[off_log + b * 10 + n] = slog[n];
        }
    }
}

// ---------------- launch ------------------------------------------------------
extern "C" void kernel_launch(void* const* d_in, const int* in_sizes, int n_in,
                              void* d_out, int out_size) {
    const float* X  = (const float*)d_in[0];
    const float* h  = (const float*)d_in[1];
    const float* W0 = (const float*)d_in[2];
    const float* Ws = (const float*)d_in[3];
    const float* bs = (const float*)d_in[4];
    const float* Wc = (const float*)d_in[5];
    const float* bc = (const float*)d_in[6];
    float* out = (float*)d_out;

    int off_log = -1, off_xt = -1;
    if (out_size >= 10240 + 10240 + 53477376) { off_log = 10240; off_xt = 20480; }
    else if (out_size == 10240 + 53477376)    { off_xt = 10240; }
    else if (out_size >= 20480)               { off_log = 10240; }

    cudaFuncSetAttribute(tgemm_kernel, cudaFuncAttributeMaxDynamicSharedMemorySize,
                         SMEM_TOTAL_G);

    wconv_kernel<<<WELEMS / 256, 256>>>(W0, Ws);
    prep_kernel<<<PLANE / 256, 256>>>(X);

    tgemm_kernel<<<192, 256, SMEM_TOTAL_G>>>(nullptr, h, 0);
    polar_kernel<<<512, 128>>>(0, 4, 6, 1);       // layer 0: 4 aggressive + 6 classic
    for (int l = 1; l <= 16; l++) {
        tgemm_kernel<<<192, 256, SMEM_TOTAL_G>>>(bs + (size_t)(l - 1) * 1024, h, l);
        polar_kernel<<<512, 128>>>(l, 0, 6, (l + 1) & 1);   // near-orthogonal: 6 classic
    }

    if (off_xt >= 0)
        xt_kernel<<<PLANE / 256, 256>>>(out + off_xt);
    classify_kernel<<<1024, 128>>>(Wc, bc, out, off_log);
}

// round 7
// speedup vs baseline: 2.8458x; 1.2298x over previous
#include <cuda_runtime.h>
#include <cuda_fp16.h>
#include <math.h>
#include <stdint.h>

#define PLANE 3145728            // 3072 * 1024
#define WELEMS 17825792          // 17 * 1024 * 1024

// ---------------- device scratch --------------------------------------------
__device__ float g_Y[PLANE];                 // pre-projection Y of current layer
__device__ float g_xt[17 * PLANE];           // xs[l] planes (fp32)
__device__ __half g_hX[2][PLANE];            // ping-pong fp16 X
__device__ __half g_hW[WELEMS];              // fp16 weights (W0 at 0, Ws at 1..16)

// ---------------- helpers -----------------------------------------------------
static __device__ __forceinline__ uint32_t smem_u32(const void* p) {
    return (uint32_t)__cvta_generic_to_shared(p);
}
static __device__ __forceinline__ void ldsm4(uint32_t* r, uint32_t addr) {
    asm volatile("ldmatrix.sync.aligned.m8n8.x4.shared.b16 {%0,%1,%2,%3}, [%4];"
        : "=r"(r[0]), "=r"(r[1]), "=r"(r[2]), "=r"(r[3]) : "r"(addr));
}
static __device__ __forceinline__ void mma16816(float* c, const uint32_t* a,
                                                uint32_t b0, uint32_t b1) {
    asm volatile("mma.sync.aligned.m16n8k16.row.col.f32.f16.f16.f32 "
        "{%0,%1,%2,%3}, {%4,%5,%6,%7}, {%8,%9}, {%0,%1,%2,%3};"
        : "+f"(c[0]), "+f"(c[1]), "+f"(c[2]), "+f"(c[3])
        : "r"(a[0]), "r"(a[1]), "r"(a[2]), "r"(a[3]), "r"(b0), "r"(b1));
}

// ---------------- weight conversion (fp16) -----------------------------------
__global__ void wconv_kernel(const float* __restrict__ W0, const float* __restrict__ Ws) {
    size_t i = (size_t)blockIdx.x * 256 + threadIdx.x;
    if (i >= (size_t)WELEMS) return;
    float v = (i < 1048576) ? W0[i] : Ws[i - 1048576];
    g_hW[i] = __float2half_rn(v);
}

// ---------------- prep: fp16 of input (ch2 transposed) -----------------------
__global__ void prep_kernel(const float* __restrict__ Xin) {
    int idx = blockIdx.x * 256 + threadIdx.x;
    if (idx >= PLANE) return;
    int d  = idx & 1023;
    int bc = idx >> 10;
    int c  = bc % 3;
    float v;
    if (c == 2) {
        int b = bc / 3;
        int dim = d >> 4, k = d & 15;
        v = Xin[((size_t)(b * 3 + 2)) * 1024 + k * 64 + dim];
    } else {
        v = Xin[idx];
    }
    g_hX[0][idx] = __float2half_rn(v);
}

// ---------------- fp16 mma.sync GEMM + fused epilogue ------------------------
// D[m,n] = sum_d A[m,d]*W[n,d], single fp16 product.
// Tile 96x128 (256 CTAs -> better wave fill), K-chunk 32, 3-stage cp.async,
// 8 warps (2M x 4N), warp tile 48x32.
#define MAT_STRIDE_B 80                  // bytes per smem row (pad, conflict-free)
#define A_BYTES (96 * MAT_STRIDE_B)      // 7680
#define B_BYTES (128 * MAT_STRIDE_B)     // 10240
#define STAGE_BYTES (A_BYTES + B_BYTES)  // 17920
#define SMEM_TOTAL_G (3 * STAGE_BYTES)   // 53760

__global__ __launch_bounds__(256, 2) void tgemm_kernel(
    const float* __restrict__ bias, const float* __restrict__ hp, int layer)
{
    extern __shared__ __align__(16) char smem[];
    uint32_t sb = smem_u32(smem);

    int tid = threadIdx.x;
    int wid = tid >> 5, lane = tid & 31;
    int bx = blockIdx.x;
    int m0 = (bx >> 3) * 96;
    int n0 = (bx & 7) * 128;

    int par = layer & 1;
    const __half* srcA = g_hX[par] + (size_t)m0 * 1024;
    const __half* srcB = g_hW + (size_t)layer * 1048576 + (size_t)n0 * 1024;

    float acc[3][4][4];
#pragma unroll
    for (int i = 0; i < 3; i++)
#pragma unroll
        for (int j = 0; j < 4; j++)
#pragma unroll
            for (int k = 0; k < 4; k++) acc[i][j][k] = 0.f;

    auto issue = [&](int c, int st) {
#pragma unroll
        for (int u = 0; u < 4; u++) {
            int unit = tid + u * 256;        // 0..1023, use 0..895
            if (unit < 896) {
                uint32_t dst;
                const __half* gp;
                if (unit < 384) {            // A: 96 rows x 4 segs
                    int row = unit >> 2, seg = unit & 3;
                    dst = sb + st * STAGE_BYTES + row * MAT_STRIDE_B + seg * 16;
                    gp = srcA + (size_t)row * 1024 + c * 32 + seg * 8;
                } else {                     // B: 128 rows x 4 segs
                    int t = unit - 384;
                    int row = t >> 2, seg = t & 3;
                    dst = sb + st * STAGE_BYTES + A_BYTES + row * MAT_STRIDE_B + seg * 16;
                    gp = srcB + (size_t)row * 1024 + c * 32 + seg * 8;
                }
                asm volatile("cp.async.cg.shared.global [%0], [%1], 16;"
                    :: "r"(dst), "l"(gp));
            }
        }
        asm volatile("cp.async.commit_group;" ::: "memory");
    };

    issue(0, 0);
    issue(1, 1);

    int mw = (wid >> 2) * 48, nw = (wid & 3) * 32;
    int lrow = (lane & 7) + ((lane >> 3) & 1) * 8;
    int lcolB = ((lane >> 4) * 8) * 2;   // byte offset of ldmatrix col

    for (int c = 0; c < 32; c++) {
        int st = c % 3;
        if (c + 2 < 32) {
            issue(c + 2, (c + 2) % 3);
            asm volatile("cp.async.wait_group 2;" ::: "memory");
        } else if (c + 1 < 32) {
            asm volatile("cp.async.wait_group 1;" ::: "memory");
        } else {
            asm volatile("cp.async.wait_group 0;" ::: "memory");
        }
        __syncthreads();

        uint32_t base = sb + st * STAGE_BYTES;
#pragma unroll
        for (int ks = 0; ks < 2; ks++) {
            int colb = ks * 32 + lcolB;
            uint32_t bh[2][4];
#pragma unroll
            for (int nb = 0; nb < 2; nb++)
                ldsm4(bh[nb], base + A_BYTES +
                              (nw + nb * 16 + lrow) * MAT_STRIDE_B + colb);
#pragma unroll
            for (int ma = 0; ma < 3; ma++) {
                uint32_t ah[4];
                ldsm4(ah, base + (mw + ma * 16 + lrow) * MAT_STRIDE_B + colb);
#pragma unroll
                for (int na = 0; na < 4; na++) {
                    int nb = na >> 1, hi = na & 1;
                    mma16816(acc[ma][na], ah, bh[nb][hi], bh[nb][2 + hi]);
                }
            }
        }
        __syncthreads();
    }

    // ---- fused epilogue from register fragments
    float hv = 0.f;
    const float* Xprev = nullptr;
    if (layer > 0) { hv = *hp; Xprev = g_xt + (size_t)(layer - 1) * PLANE; }
    float* PL = g_xt + (size_t)layer * PLANE;
    int opar = (layer + 1) & 1;
    int g = lane >> 2, t2 = (lane & 3) * 2;

#pragma unroll
    for (int ma = 0; ma < 3; ma++) {
#pragma unroll
        for (int na = 0; na < 4; na++) {
            int n = n0 + nw + na * 8 + t2;
            float2 b2 = make_float2(0.f, 0.f);
            if (layer > 0) b2 = *(const float2*)(bias + n);
#pragma unroll
            for (int hh = 0; hh < 2; hh++) {
                int m = m0 + mw + ma * 16 + g + hh * 8;
                float cx = acc[ma][na][hh * 2], cy = acc[ma][na][hh * 2 + 1];
                float2 y;
                if (layer > 0) {
                    float2 xo = *(const float2*)(Xprev + (size_t)m * 1024 + n);
                    y.x = xo.x + hv * fmaxf(cx + b2.x, 0.f);
                    y.y = xo.y + hv * fmaxf(cy + b2.y, 0.f);
                } else {
                    y.x = cx; y.y = cy;
                }
                *(float2*)(g_Y + (size_t)m * 1024 + n) = y;
                if (m % 3 == 1) {
                    *(float2*)(PL + (size_t)m * 1024 + n) = y;
                    __half2 h2;
                    h2.x = __float2half_rn(y.x);
                    h2.y = __float2half_rn(y.y);
                    *(__half2*)(&g_hX[opar][(size_t)m * 1024 + n]) = h2;
                }
            }
        }
    }
}

// ---------------- polar projection (tuned Newton-Schulz on 16x16 Gram) -------
// Coupled iteration Y<-Y*T, Z<-T*Z with T = a*I + b*(Z*Y).
// First nspecial steps use (ca,cb); remaining steps classic (1.5,-0.5).
#define PNW 4
__global__ __launch_bounds__(128) void polar_kernel(int plane, int nspecial,
                                                    int nclassic, float ca_s,
                                                    float cb_s, int opar) {
    __shared__ float AsP[PNW][16][68];
    __shared__ float MsP[PNW][3][16][20];

    int w = threadIdx.x >> 5, lane = threadIdx.x & 31;
    int idx = blockIdx.x * PNW + w;
    int b = idx >> 1, ch = (idx & 1) * 2;

    const float* src = g_Y + (size_t)(b * 3 + ch) * 1024;
    size_t doff = (size_t)(b * 3 + ch) * 1024;
    float* dst = g_xt + (size_t)plane * PLANE + doff;

    float (*A)[68]  = AsP[w];
    float (*Ym)[20] = MsP[w][0];
    float (*Zm)[20] = MsP[w][1];
    float (*Tm)[20] = MsP[w][2];

    int r0 = lane * 2;
#pragma unroll
    for (int qq = 0; qq < 4; qq++) {
        float4 v0 = *(const float4*)(src + r0 * 16 + qq * 4);
        float4 v1 = *(const float4*)(src + (r0 + 1) * 16 + qq * 4);
        A[qq * 4 + 0][r0] = v0.x; A[qq * 4 + 1][r0] = v0.y;
        A[qq * 4 + 2][r0] = v0.z; A[qq * 4 + 3][r0] = v0.w;
        A[qq * 4 + 0][r0 + 1] = v1.x; A[qq * 4 + 1][r0 + 1] = v1.y;
        A[qq * 4 + 2][r0 + 1] = v1.z; A[qq * 4 + 3][r0 + 1] = v1.w;
    }
    __syncwarp();

    int i0 = (lane >> 2) * 2, j0 = (lane & 3) * 4;
    float g0[4] = {0, 0, 0, 0}, g1[4] = {0, 0, 0, 0};
#pragma unroll
    for (int r = 0; r < 64; r += 4) {
        float4 a0 = *(const float4*)&A[i0][r];
        float4 a1 = *(const float4*)&A[i0 + 1][r];
#pragma unroll
        for (int t = 0; t < 4; t++) {
            float4 aj = *(const float4*)&A[j0 + t][r];
            g0[t] += a0.x * aj.x + a0.y * aj.y + a0.z * aj.z + a0.w * aj.w;
            g1[t] += a1.x * aj.x + a1.y * aj.y + a1.z * aj.z + a1.w * aj.w;
        }
    }
    *(float4*)&Ym[i0][j0]     = make_float4(g0[0], g0[1], g0[2], g0[3]);
    *(float4*)&Ym[i0 + 1][j0] = make_float4(g1[0], g1[1], g1[2], g1[3]);
    __syncwarp();

    float rs = 0.f;
    if (lane < 16) {
#pragma unroll
        for (int j = 0; j < 16; j++) rs += fabsf(Ym[lane][j]);
    }
#pragma unroll
    for (int off = 16; off; off >>= 1)
        rs = fmaxf(rs, __shfl_xor_sync(0xffffffffu, rs, off));
    float invs = 1.0f / rs;

#pragma unroll
    for (int t = 0; t < 4; t++) { g0[t] *= invs; g1[t] *= invs; }
    *(float4*)&Ym[i0][j0]     = make_float4(g0[0], g0[1], g0[2], g0[3]);
    *(float4*)&Ym[i0 + 1][j0] = make_float4(g1[0], g1[1], g1[2], g1[3]);
    *(float4*)&Zm[i0][j0] = make_float4(i0 == j0 ? 1.f : 0.f, i0 == j0 + 1 ? 1.f : 0.f,
                                        i0 == j0 + 2 ? 1.f : 0.f, i0 == j0 + 3 ? 1.f : 0.f);
    *(float4*)&Zm[i0 + 1][j0] = make_float4(i0 + 1 == j0 ? 1.f : 0.f, i0 + 1 == j0 + 1 ? 1.f : 0.f,
                                            i0 + 1 == j0 + 2 ? 1.f : 0.f, i0 + 1 == j0 + 3 ? 1.f : 0.f);
    __syncwarp();

    int ntot = nspecial + nclassic;
    for (int it = 0; it < ntot; it++) {
        float ca = (it < nspecial) ? ca_s : 1.5f;
        float cb = (it < nspecial) ? cb_s : -0.5f;
        float t0[4] = {0, 0, 0, 0}, t1[4] = {0, 0, 0, 0};
#pragma unroll
        for (int k = 0; k < 16; k++) {
            float z0 = Zm[i0][k], z1 = Zm[i0 + 1][k];
            float4 y4 = *(const float4*)&Ym[k][j0];
            t0[0] += z0 * y4.x; t0[1] += z0 * y4.y; t0[2] += z0 * y4.z; t0[3] += z0 * y4.w;
            t1[0] += z1 * y4.x; t1[1] += z1 * y4.y; t1[2] += z1 * y4.z; t1[3] += z1 * y4.w;
        }
#pragma unroll
        for (int t = 0; t < 4; t++) {
            t0[t] = ((i0     == j0 + t) ? ca : 0.f) + cb * t0[t];
            t1[t] = ((i0 + 1 == j0 + t) ? ca : 0.f) + cb * t1[t];
        }
        *(float4*)&Tm[i0][j0]     = make_float4(t0[0], t0[1], t0[2], t0[3]);
        *(float4*)&Tm[i0 + 1][j0] = make_float4(t1[0], t1[1], t1[2], t1[3]);
        __syncwarp();

        float yn0[4] = {0, 0, 0, 0}, yn1[4] = {0, 0, 0, 0};
        float zn0[4] = {0, 0, 0, 0}, zn1[4] = {0, 0, 0, 0};
#pragma unroll
        for (int k = 0; k < 16; k++) {
            float4 t4 = *(const float4*)&Tm[k][j0];
            float ya = Ym[i0][k], yb = Ym[i0 + 1][k];
            yn0[0] += ya * t4.x; yn0[1] += ya * t4.y; yn0[2] += ya * t4.z; yn0[3] += ya * t4.w;
            yn1[0] += yb * t4.x; yn1[1] += yb * t4.y; yn1[2] += yb * t4.z; yn1[3] += yb * t4.w;
            float4 z4 = *(const float4*)&Zm[k][j0];
            float ta = Tm[i0][k], tb = Tm[i0 + 1][k];
            zn0[0] += ta * z4.x; zn0[1] += ta * z4.y; zn0[2] += ta * z4.z; zn0[3] += ta * z4.w;
            zn1[0] += tb * z4.x; zn1[1] += tb * z4.y; zn1[2] += tb * z4.z; zn1[3] += tb * z4.w;
        }
        __syncwarp();
        *(float4*)&Ym[i0][j0]     = make_float4(yn0[0], yn0[1], yn0[2], yn0[3]);
        *(float4*)&Ym[i0 + 1][j0] = make_float4(yn1[0], yn1[1], yn1[2], yn1[3]);
        *(float4*)&Zm[i0][j0]     = make_float4(zn0[0], zn0[1], zn0[2], zn0[3]);
        *(float4*)&Zm[i0 + 1][j0] = make_float4(zn1[0], zn1[1], zn1[2], zn1[3]);
        __syncwarp();
    }

    float isq = rsqrtf(rs);
    float u0[16], u1[16];
#pragma unroll
    for (int c = 0; c < 16; c++) { u0[c] = 0.f; u1[c] = 0.f; }
#pragma unroll
    for (int k = 0; k < 16; k++) {
        float a0 = A[k][r0], a1 = A[k][r0 + 1];
#pragma unroll
        for (int cq = 0; cq < 4; cq++) {
            float4 z4 = *(const float4*)&Zm[k][cq * 4];
            u0[cq * 4 + 0] += a0 * z4.x; u0[cq * 4 + 1] += a0 * z4.y;
            u0[cq * 4 + 2] += a0 * z4.z; u0[cq * 4 + 3] += a0 * z4.w;
            u1[cq * 4 + 0] += a1 * z4.x; u1[cq * 4 + 1] += a1 * z4.y;
            u1[cq * 4 + 2] += a1 * z4.z; u1[cq * 4 + 3] += a1 * z4.w;
        }
    }
#pragma unroll
    for (int c = 0; c < 16; c++) { u0[c] *= isq; u1[c] *= isq; }

    // fp32 U out
#pragma unroll
    for (int cq = 0; cq < 4; cq++) {
        *(float4*)(dst + r0 * 16 + cq * 4) =
            make_float4(u0[cq * 4], u0[cq * 4 + 1], u0[cq * 4 + 2], u0[cq * 4 + 3]);
        *(float4*)(dst + (r0 + 1) * 16 + cq * 4) =
            make_float4(u1[cq * 4], u1[cq * 4 + 1], u1[cq * 4 + 2], u1[cq * 4 + 3]);
    }

    // fp16 out: pack via smem for coalesced writes
    uint32_t phi[16];
#pragma unroll
    for (int row2 = 0; row2 < 2; row2++) {
        float* u = row2 ? u1 : u0;
#pragma unroll
        for (int cq = 0; cq < 8; cq++) {
            __half2 hp2;
            hp2.x = __float2half_rn(u[2 * cq]);
            hp2.y = __float2half_rn(u[2 * cq + 1]);
            phi[row2 * 8 + cq] = *(uint32_t*)&hp2;
        }
    }
    __syncwarp();
    uint32_t* pk = (uint32_t*)&A[0][0];
#pragma unroll
    for (int row2 = 0; row2 < 2; row2++)
#pragma unroll
        for (int cq = 0; cq < 8; cq++) pk[(r0 + row2) * 8 + cq] = phi[row2 * 8 + cq];
    __syncwarp();
    {
        uint32_t* gd = (uint32_t*)(g_hX[opar] + doff);
#pragma unroll
        for (int i = 0; i < 16; i++) gd[lane + 32 * i] = pk[lane + 32 * i];
    }
}

// ---------------- X_transformed transpose ------------------------------------
__global__ void xt_kernel(float* __restrict__ out) {
    __shared__ float tile[256][18];
    int base = blockIdx.x * 256;
    int tid = threadIdx.x;
#pragma unroll
    for (int l = 0; l < 17; l++)
        tile[tid][l] = g_xt[(size_t)l * PLANE + base + tid];
    __syncthreads();
    float* o = out + (size_t)base * 17;
    for (int i = tid; i < 256 * 17; i += 256)
        o[i] = tile[i / 17][i % 17];
}

// ---------------- reconstruct + classify + softmax ----------------------------
__global__ __launch_bounds__(128) void classify_kernel(
    const float* __restrict__ Wc, const float* __restrict__ bc,
    float* __restrict__ out, int off_log)
{
    __shared__ float sU[1024], sS[256], sV[1024], sT[1024];
    __shared__ float sZ[4096];
    __shared__ float red[10 * 136];
    __shared__ float slog[10];

    int b = blockIdx.x, tid = threadIdx.x;
    const float* base = g_xt + (size_t)16 * PLANE + (size_t)b * 3 * 1024;

    for (int i = tid; i < 1024; i += 128) { sU[i] = base[i]; sV[i] = base[2048 + i]; }
    for (int i = tid; i < 256; i += 128) sS[i] = base[1024 + i];
    __syncthreads();

    for (int e = tid; e < 1024; e += 128) {
        int r = e >> 4, c = e & 15;
        float sum = 0.f;
#pragma unroll
        for (int k = 0; k < 16; k++) sum += sU[r * 16 + k] * sS[k * 16 + c];
        sT[e] = sum;
    }
    __syncthreads();

    for (int e = tid; e < 4096; e += 128) {
        int r = e >> 6, qn = e & 63;
        float sum = 0.f;
#pragma unroll
        for (int c = 0; c < 16; c++) sum += sT[r * 16 + c] * sV[qn * 16 + c];
        sZ[e] = sum;
    }
    __syncthreads();

    float acc[10];
#pragma unroll
    for (int n = 0; n < 10; n++) acc[n] = 0.f;
    for (int e = tid; e < 4096; e += 128) {
        float z = sZ[e];
#pragma unroll
        for (int n = 0; n < 10; n++) acc[n] += z * Wc[n * 4096 + e];
    }
#pragma unroll
    for (int n = 0; n < 10; n++) red[n * 136 + tid] = acc[n];
    __syncthreads();
    if (tid < 10) {
        float s = bc[tid];
        for (int j = 0; j < 128; j++) s += red[tid * 136 + j];
        slog[tid] = s;
    }
    __syncthreads();
    if (tid == 0) {
        float mx = slog[0];
        for (int n = 1; n < 10; n++) mx = fmaxf(mx, slog[n]);
        float ex[10]; float se = 0.f;
        for (int n = 0; n < 10; n++) { ex[n] = expf(slog[n] - mx); se += ex[n]; }
        float inv = 1.f / se;
        for (int n = 0; n < 10; n++) {
            out[b * 10 + n] = ex[n] * inv;
            if (off_log >= 0) out[off_log + b * 10 + n] = slog[n];
        }
    }
}

// ---------------- launch ------------------------------------------------------
extern "C" void kernel_launch(void* const* d_in, const int* in_sizes, int n_in,
                              void* d_out, int out_size) {
    const float* X  = (const float*)d_in[0];
    const float* h  = (const float*)d_in[1];
    const float* W0 = (const float*)d_in[2];
    const float* Ws = (const float*)d_in[3];
    const float* bs = (const float*)d_in[4];
    const float* Wc = (const float*)d_in[5];
    const float* bc = (const float*)d_in[6];
    float* out = (float*)d_out;

    int off_log = -1, off_xt = -1;
    if (out_size >= 10240 + 10240 + 53477376) { off_log = 10240; off_xt = 20480; }
    else if (out_size == 10240 + 53477376)    { off_xt = 10240; }
    else if (out_size >= 20480)               { off_log = 10240; }

    cudaFuncSetAttribute(tgemm_kernel, cudaFuncAttributeMaxDynamicSharedMemorySize,
                         SMEM_TOTAL_G);

    wconv_kernel<<<WELEMS / 256, 256>>>(W0, Ws);
    prep_kernel<<<PLANE / 256, 256>>>(X);

    tgemm_kernel<<<256, 256, SMEM_TOTAL_G>>>(nullptr, h, 0);
    polar_kernel<<<512, 128>>>(0, 4, 6, 2.4f, -1.4f, 1);   // layer 0: 4 agg + 6 classic
    for (int l = 1; l <= 16; l++) {
        tgemm_kernel<<<256, 256, SMEM_TOTAL_G>>>(bs + (size_t)(l - 1) * 1024, h, l);
        polar_kernel<<<512, 128>>>(l, 1, 3, 1.9f, -0.9f, (l + 1) & 1);  // 1 tuned + 3 classic
    }

    if (off_xt >= 0)
        xt_kernel<<<PLANE / 256, 256>>>(out + off_xt);
    classify_kernel<<<1024, 128>>>(Wc, bc, out, off_log);
}